// round 2
// baseline (speedup 1.0000x reference)
#include <cuda_runtime.h>
#include <math.h>

typedef unsigned long long ull;

// ---------------------------------------------------------------- constants
#define NB   64
#define NS   512
#define NH   512
#define NA   512
#define NCC  4
#define NV   1000
#define NED  128
#define NFF  6
#define BS   32768          // NB*NS

// ---------------------------------------------------------------- scratch
__device__ float g_CE[BS * NH];       // gathered embeddings; reused as scores
__device__ float g_X [BS * NH];       // x; reused as z
__device__ float g_Q [BS * NA];       // Q; reused as Zt
__device__ float g_K [BS * NA];       // K; reused as GRU layer-0 output
__device__ float g_V [BS * NA];       // V; reused as GRU layer-1 output
__device__ float g_GI[BS * 3 * NA];   // GRU input gates (per layer)
__device__ float g_h [2][NB * NA];    // double-buffered hidden state
__device__ float g_Wcc[NFF * NH];
__device__ float g_bcc[NH];
__device__ unsigned g_cnt = 0;
__device__ volatile unsigned g_phase = 0;

// ---------------------------------------------------------------- f32x2 fma
__device__ __forceinline__ ull pk(float a, float b) {
    ull r; asm("mov.b64 %0,{%1,%2};" : "=l"(r) : "f"(a), "f"(b)); return r;
}
__device__ __forceinline__ void fma2(ull& d, ull a, ull b) {
    asm("fma.rn.f32x2 %0,%1,%2,%0;" : "+l"(d) : "l"(a), "l"(b));
}
__device__ __forceinline__ float2 upk(ull v) {
    float2 f; asm("mov.b64 {%0,%1},%2;" : "=f"(f.x), "=f"(f.y) : "l"(v)); return f;
}
__device__ __forceinline__ float sigm(float x) { return 1.f / (1.f + expf(-x)); }

// ---------------------------------------------------------------- prep
// Wcc = W_cont @ Wcomb[512:], bcc = b_cont @ Wcomb[512:] + b_comb
__global__ void k_prep(const float* __restrict__ Wcont, const float* __restrict__ bcont,
                       const float* __restrict__ Wcomb, const float* __restrict__ bcomb) {
    int j = blockIdx.x * 256 + threadIdx.x;
    if (j >= NH) return;
    float acc[NFF];
#pragma unroll
    for (int f = 0; f < NFF; f++) acc[f] = 0.f;
    float bacc = bcomb[j];
    for (int m = 0; m < NH; m++) {
        float w2 = Wcomb[(NH + m) * NH + j];
        bacc += bcont[m] * w2;
#pragma unroll
        for (int f = 0; f < NFF; f++) acc[f] += Wcont[f * NH + m] * w2;
    }
#pragma unroll
    for (int f = 0; f < NFF; f++) g_Wcc[f * NH + j] = acc[f];
    g_bcc[j] = bacc;
}

// ---------------------------------------------------------------- gather
__global__ void k_gather(const int* __restrict__ cate, const float* __restrict__ emb) {
    long i = (long)blockIdx.x * 256 + threadIdx.x;
    int n = (int)(i >> 9);
    int col = (int)(i & 511);
    int c = col >> 7, e = col & 127;
    int idx = cate[n * NCC + c];
    g_CE[i] = emb[((long)c * NV + idx) * NED + e];
}

// ---------------------------------------------------------------- extras
// x += cont@Wcc + bcc + positional encoding
__global__ void k_extras(const float* __restrict__ cont) {
    int n = blockIdx.x;
    int j2 = threadIdx.x;
    __shared__ float c[NFF];
    if (threadIdx.x < NFF) c[threadIdx.x] = cont[n * NFF + threadIdx.x];
    __syncthreads();
    int s = n & (NS - 1);
    int j = j2 * 2;
    float v0 = g_bcc[j], v1 = g_bcc[j + 1];
#pragma unroll
    for (int f = 0; f < NFF; f++) {
        float cf = c[f];
        v0 += cf * g_Wcc[f * NH + j];
        v1 += cf * g_Wcc[f * NH + j + 1];
    }
    float ang = (float)s * expf(-(float)j * 0.0179889460f); // ln(10000)/512
    float sn, cs; sincosf(ang, &sn, &cs);
    v0 += sn; v1 += cs;
    float2* px = (float2*)(g_X + (long)n * NH);
    float2 o = px[j2];
    px[j2] = make_float2(o.x + v0, o.y + v1);
}

// ---------------------------------------------------------------- GEMM
// C[M,N] = scale*(A @ op(B)) + bias; A:[M,K] rm. TRB=0: B:[K,N]; TRB=1: B:[N,K]
#define BM 128
#define BN 64
#define BK 16

template <int TRB>
__global__ __launch_bounds__(256) void k_gemm(
    const float* __restrict__ A, const float* __restrict__ Bm, float* __restrict__ C,
    int N, int K, long sA, long sB, long sC, const float* __restrict__ bias, float scale) {
    __shared__ float As[BK][BM + 4];
    __shared__ float Bs[BK][BN + 4];
    A += (long)blockIdx.z * sA;
    Bm += (long)blockIdx.z * sB;
    C += (long)blockIdx.z * sC;
    int m0 = blockIdx.y * BM, n0 = blockIdx.x * BN;
    int t = threadIdx.x;
    int tx = t & 15, ty = t >> 4;
    ull acc[4][4];
#pragma unroll
    for (int i = 0; i < 4; i++)
#pragma unroll
        for (int j = 0; j < 4; j++) acc[i][j] = 0ULL;

    for (int k0 = 0; k0 < K; k0 += BK) {
        __syncthreads();
#pragma unroll
        for (int r = 0; r < 2; r++) {
            int q = t + r * 256;
            int am = q >> 2, ak = (q & 3) * 4;
            float4 v = *(const float4*)(A + (long)(m0 + am) * K + k0 + ak);
            As[ak + 0][am] = v.x; As[ak + 1][am] = v.y;
            As[ak + 2][am] = v.z; As[ak + 3][am] = v.w;
        }
        if (TRB == 0) {
            int bk = t >> 4, bn = (t & 15) * 4;
            *(float4*)&Bs[bk][bn] = *(const float4*)(Bm + (long)(k0 + bk) * N + n0 + bn);
        } else {
            int bn = t >> 2, bk = (t & 3) * 4;
            float4 v = *(const float4*)(Bm + (long)(n0 + bn) * K + k0 + bk);
            Bs[bk + 0][bn] = v.x; Bs[bk + 1][bn] = v.y;
            Bs[bk + 2][bn] = v.z; Bs[bk + 3][bn] = v.w;
        }
        __syncthreads();
#pragma unroll
        for (int kk = 0; kk < BK; kk++) {
            ulonglong2 t0 = *(const ulonglong2*)&As[kk][ty * 8];
            ulonglong2 t1 = *(const ulonglong2*)&As[kk][ty * 8 + 4];
            ull av0 = t0.x, av1 = t0.y, av2 = t1.x, av3 = t1.y;
            float4 b4 = *(const float4*)&Bs[kk][tx * 4];
            ull b0 = pk(b4.x, b4.x), b1 = pk(b4.y, b4.y);
            ull b2 = pk(b4.z, b4.z), b3 = pk(b4.w, b4.w);
            fma2(acc[0][0], av0, b0); fma2(acc[0][1], av0, b1);
            fma2(acc[0][2], av0, b2); fma2(acc[0][3], av0, b3);
            fma2(acc[1][0], av1, b0); fma2(acc[1][1], av1, b1);
            fma2(acc[1][2], av1, b2); fma2(acc[1][3], av1, b3);
            fma2(acc[2][0], av2, b0); fma2(acc[2][1], av2, b1);
            fma2(acc[2][2], av2, b2); fma2(acc[2][3], av2, b3);
            fma2(acc[3][0], av3, b0); fma2(acc[3][1], av3, b1);
            fma2(acc[3][2], av3, b2); fma2(acc[3][3], av3, b3);
        }
    }
    float4 bb = make_float4(0.f, 0.f, 0.f, 0.f);
    if (bias) bb = *(const float4*)(bias + n0 + tx * 4);
#pragma unroll
    for (int i = 0; i < 4; i++) {
        float2 e0 = upk(acc[i][0]), e1 = upk(acc[i][1]);
        float2 e2 = upk(acc[i][2]), e3 = upk(acc[i][3]);
        float4 lo = make_float4(e0.x * scale + bb.x, e1.x * scale + bb.y,
                                e2.x * scale + bb.z, e3.x * scale + bb.w);
        float4 hi = make_float4(e0.y * scale + bb.x, e1.y * scale + bb.y,
                                e2.y * scale + bb.z, e3.y * scale + bb.w);
        int m = m0 + ty * 8 + 2 * i;
        *(float4*)(C + (long)m * N + n0 + tx * 4) = lo;
        *(float4*)(C + (long)(m + 1) * N + n0 + tx * 4) = hi;
    }
}

// ---------------------------------------------------------------- softmax over q (axis=1)
__global__ void k_softmax(float* __restrict__ P) {
    int tid = blockIdx.x * 256 + threadIdx.x;       // 32768 = b*512+k
    int b = tid >> 9, k = tid & 511;
    float* p = P + (long)b * (NS * NS) + k;
    float m = -1e30f;
    for (int q = 0; q < NS; q++) m = fmaxf(m, p[q * NS]);
    float s = 0.f;
    for (int q = 0; q < NS; q++) { float e = __expf(p[q * NS] - m); s += e; p[q * NS] = e; }
    float inv = 1.f / s;
    for (int q = 0; q < NS; q++) p[q * NS] *= inv;
}

// ---------------------------------------------------------------- z[b,s,:] -> Zt[(s,b),:]
__global__ void k_perm(const float4* __restrict__ in, float4* __restrict__ out) {
    long tid = (long)blockIdx.x * 256 + threadIdx.x;   // BS*128
    int row = (int)(tid >> 7), c = (int)(tid & 127);
    int s = row >> 6, b = row & 63;
    out[(long)row * 128 + c] = in[((long)b * NS + s) * 128 + c];
}

__global__ void k_zero(float* p, int n) {
    int i = blockIdx.x * 256 + threadIdx.x;
    if (i < n) p[i] = 0.f;
}

// ---------------------------------------------------------------- grid barrier
__device__ __forceinline__ void gbar() {
    __syncthreads();
    if (threadIdx.x == 0) {
        unsigned gen = g_phase;
        __threadfence();
        if (atomicAdd(&g_cnt, 1u) == gridDim.x - 1u) {
            g_cnt = 0;
            __threadfence();
            g_phase = gen + 1u;
        } else {
            while (g_phase == gen) { }
            __threadfence();
        }
    }
    __syncthreads();
}

// ---------------------------------------------------------------- persistent GRU layer
// 128 CTAs x 256 threads. CTA owns 4 hidden units (all 3 gates). Wh slice in SMEM.
__global__ __launch_bounds__(256) void k_gru(const float* __restrict__ GI,
                                             const float* __restrict__ Wh,
                                             const float* __restrict__ bh,
                                             float* __restrict__ Hout) {
    __shared__ float ws[12][516];
    int t = threadIdx.x;
    int u0 = blockIdx.x * 4;
    for (int r = 0; r < 12; r++) {
        int gate = r >> 2, i = r & 3;
        const float* src = Wh + (long)(gate * NA + u0 + i) * NA;
        for (int k = t; k < NA; k += 256) ws[r][k] = src[k];
    }
    __syncthreads();
    int b = t >> 2, jg = t & 3;
    int u = u0 + jg;
    float bhr = bh[u], bhz = bh[NA + u], bhn = bh[2 * NA + u];

    for (int s = 0; s < NS; s++) {
        const float* hc = g_h[s & 1];
        float* hn = g_h[(s & 1) ^ 1];
        const float4* hv = (const float4*)(hc + b * NA);
        ull a0 = 0, a1 = 0, a2 = 0, a3 = 0, a4 = 0, a5 = 0;
#pragma unroll 4
        for (int k = 0; k < 128; k++) {
            float4 h4 = __ldcg(hv + k);
            ull hx = pk(h4.x, h4.y), hy = pk(h4.z, h4.w);
            ulonglong2 wr = *(const ulonglong2*)&ws[jg][k * 4];
            ulonglong2 wz = *(const ulonglong2*)&ws[4 + jg][k * 4];
            ulonglong2 wn = *(const ulonglong2*)&ws[8 + jg][k * 4];
            fma2(a0, hx, wr.x); fma2(a1, hy, wr.y);
            fma2(a2, hx, wz.x); fma2(a3, hy, wz.y);
            fma2(a4, hx, wn.x); fma2(a5, hy, wn.y);
        }
        float2 r0 = upk(a0), r1 = upk(a1);
        float2 z0 = upk(a2), z1 = upk(a3);
        float2 n0 = upk(a4), n1 = upk(a5);
        float ar = r0.x + r0.y + r1.x + r1.y;
        float az = z0.x + z0.y + z1.x + z1.y;
        float an = n0.x + n0.y + n1.x + n1.y;

        long m = (long)s * NB + b;
        const float* gi = GI + m * (3 * NA);
        float gr = __ldg(gi + u), gz = __ldg(gi + NA + u), gn = __ldg(gi + 2 * NA + u);
        float r = sigm(gr + ar + bhr);
        float z = sigm(gz + az + bhz);
        float n = tanhf(gn + r * (an + bhn));
        float hp = __ldcg(&hc[b * NA + u]);
        float hval = (1.f - z) * n + z * hp;
        hn[b * NA + u] = hval;
        Hout[m * NA + u] = hval;
        __threadfence();
        gbar();
    }
}

// ---------------------------------------------------------------- head
__global__ void k_head(const float* __restrict__ Hs, const float* __restrict__ Wf,
                       const float* __restrict__ bf, float* __restrict__ out) {
    int warp = (blockIdx.x * 256 + threadIdx.x) >> 5;   // row (s,b)
    int lane = threadIdx.x & 31;
    const float* row = Hs + (long)warp * NA;
    float s = 0.f;
#pragma unroll
    for (int i = 0; i < 16; i++) s += row[lane + i * 32] * __ldg(&Wf[lane + i * 32]);
#pragma unroll
    for (int o = 16; o; o >>= 1) s += __shfl_xor_sync(0xffffffffu, s, o);
    if (lane == 0) {
        int ss = warp >> 6, b = warp & 63;
        out[b * NS + ss] = sigm(s + __ldg(bf));
    }
}

// ---------------------------------------------------------------- launch
extern "C" void kernel_launch(void* const* d_in, const int* in_sizes, int n_in,
                              void* d_out, int out_size) {
    const int*   cate  = (const int*)d_in[0];
    const float* cont  = (const float*)d_in[1];
    const float* emb   = (const float*)d_in[4];
    const float* Wcont = (const float*)d_in[5];
    const float* bcont = (const float*)d_in[6];
    const float* Wcomb = (const float*)d_in[7];
    const float* bcomb = (const float*)d_in[8];
    const float* Wq    = (const float*)d_in[9];
    const float* Wk    = (const float*)d_in[10];
    const float* Wv    = (const float*)d_in[11];
    const float* Wi    = (const float*)d_in[12];
    const float* Wh    = (const float*)d_in[13];
    const float* bi    = (const float*)d_in[14];
    const float* bh    = (const float*)d_in[15];
    const float* Wfin  = (const float*)d_in[16];
    const float* bfin  = (const float*)d_in[17];
    float* out = (float*)d_out;

    float *CE, *X, *Q, *K, *V, *GI, *H0;
    cudaGetSymbolAddress((void**)&CE, g_CE);
    cudaGetSymbolAddress((void**)&X,  g_X);
    cudaGetSymbolAddress((void**)&Q,  g_Q);
    cudaGetSymbolAddress((void**)&K,  g_K);
    cudaGetSymbolAddress((void**)&V,  g_V);
    cudaGetSymbolAddress((void**)&GI, g_GI);
    cudaGetSymbolAddress((void**)&H0, g_h);

    const long SB2 = (long)NS * NS;   // 262144
    const float iscl = 0.0441941738241592f; // 1/sqrt(512)

    k_prep<<<2, 256>>>(Wcont, bcont, Wcomb, bcomb);
    k_gather<<<BS * NH / 256, 256>>>(cate, emb);
    // x = CE @ Wcomb[0:512]
    k_gemm<0><<<dim3(8, 256, 1), 256>>>(CE, Wcomb, X, NH, NH, 0, 0, 0, nullptr, 1.f);
    k_extras<<<BS, 256>>>(cont);
    // QKV
    k_gemm<0><<<dim3(8, 256, 1), 256>>>(X, Wq, Q, NA, NH, 0, 0, 0, nullptr, 1.f);
    k_gemm<0><<<dim3(8, 256, 1), 256>>>(X, Wk, K, NA, NH, 0, 0, 0, nullptr, 1.f);
    k_gemm<0><<<dim3(8, 256, 1), 256>>>(X, Wv, V, NA, NH, 0, 0, 0, nullptr, 1.f);
    // scores = Q @ K^T / sqrt(A)   (batched over b)
    k_gemm<1><<<dim3(8, 4, 64), 256>>>(Q, K, CE, NS, NA, SB2, SB2, SB2, nullptr, iscl);
    k_softmax<<<128, 256>>>(CE);
    // z = P @ V
    k_gemm<0><<<dim3(8, 4, 64), 256>>>(CE, V, X, NA, NS, SB2, SB2, SB2, nullptr, 1.f);
    // Zt[(s,b),:] = z[b,s,:]
    k_perm<<<BS * 128 / 256, 256>>>((const float4*)X, (float4*)Q);
    // layer 0
    k_zero<<<128, 256>>>(H0, NB * NA);
    k_gemm<1><<<dim3(24, 256, 1), 256>>>(Q, Wi, GI, 3 * NA, NA, 0, 0, 0, bi, 1.f);
    k_gru<<<128, 256>>>(GI, Wh, bh, K);
    // layer 1
    k_zero<<<128, 256>>>(H0, NB * NA);
    k_gemm<1><<<dim3(24, 256, 1), 256>>>(K, Wi + 3 * NA * NA, GI, 3 * NA, NA, 0, 0, 0,
                                         bi + 3 * NA, 1.f);
    k_gru<<<128, 256>>>(GI, Wh + 3 * NA * NA, bh + 3 * NA, V);
    // head
    k_head<<<BS / 8, 256>>>(V, Wfin, bfin, out);
}

// round 3
// speedup vs baseline: 1.1040x; 1.1040x over previous
#include <cuda_runtime.h>
#include <math.h>

typedef unsigned long long ull;
typedef unsigned int u32;

// ---------------------------------------------------------------- constants
#define NB   64
#define NS   512
#define NH   512
#define NA   512
#define NCC  4
#define NV   1000
#define NED  128
#define NFF  6
#define BS   32768          // NB*NS

// ---------------------------------------------------------------- scratch
__device__ float g_CE[BS * NH];       // gathered embeddings; reused as scores
__device__ float g_X [BS * NH];       // x; reused as z
__device__ float g_Q [BS * NA];       // Q; reused as Zt
__device__ float g_K [BS * NA];       // K; reused as GRU layer-0 output
__device__ float g_V [BS * NA];       // V; reused as GRU layer-1 output
__device__ float g_GI[BS * 3 * NA];   // GRU input gates (per layer)
__device__ float g_h [2][NB * NA];    // double-buffered hidden state
__device__ float g_Wcc[NFF * NH];
__device__ float g_bcc[NH];
__device__ unsigned g_cnt = 0;
__device__ volatile unsigned g_phase = 0;

// ---------------------------------------------------------------- helpers
__device__ __forceinline__ ull pk(float a, float b) {
    ull r; asm("mov.b64 %0,{%1,%2};" : "=l"(r) : "f"(a), "f"(b)); return r;
}
__device__ __forceinline__ void fma2(ull& d, ull a, ull b) {
    asm("fma.rn.f32x2 %0,%1,%2,%0;" : "+l"(d) : "l"(a), "l"(b));
}
__device__ __forceinline__ float2 upk(ull v) {
    float2 f; asm("mov.b64 {%0,%1},%2;" : "=f"(f.x), "=f"(f.y) : "l"(v)); return f;
}
__device__ __forceinline__ float sigm(float x) { return 1.f / (1.f + expf(-x)); }
__device__ __forceinline__ u32 f2tf(float x) {
    u32 r; asm("cvt.rna.tf32.f32 %0,%1;" : "=r"(r) : "f"(x)); return r;
}

// ---------------------------------------------------------------- prep
__global__ void k_prep(const float* __restrict__ Wcont, const float* __restrict__ bcont,
                       const float* __restrict__ Wcomb, const float* __restrict__ bcomb) {
    int j = blockIdx.x * 256 + threadIdx.x;
    if (j >= NH) return;
    float acc[NFF];
#pragma unroll
    for (int f = 0; f < NFF; f++) acc[f] = 0.f;
    float bacc = bcomb[j];
    for (int m = 0; m < NH; m++) {
        float w2 = Wcomb[(NH + m) * NH + j];
        bacc += bcont[m] * w2;
#pragma unroll
        for (int f = 0; f < NFF; f++) acc[f] += Wcont[f * NH + m] * w2;
    }
#pragma unroll
    for (int f = 0; f < NFF; f++) g_Wcc[f * NH + j] = acc[f];
    g_bcc[j] = bacc;
}

// ---------------------------------------------------------------- gather
__global__ void k_gather(const int* __restrict__ cate, const float* __restrict__ emb) {
    long i = (long)blockIdx.x * 256 + threadIdx.x;
    int n = (int)(i >> 9);
    int col = (int)(i & 511);
    int c = col >> 7, e = col & 127;
    int idx = cate[n * NCC + c];
    g_CE[i] = emb[((long)c * NV + idx) * NED + e];
}

// ---------------------------------------------------------------- extras
__global__ void k_extras(const float* __restrict__ cont) {
    int n = blockIdx.x;
    int j2 = threadIdx.x;
    __shared__ float c[NFF];
    if (threadIdx.x < NFF) c[threadIdx.x] = cont[n * NFF + threadIdx.x];
    __syncthreads();
    int s = n & (NS - 1);
    int j = j2 * 2;
    float v0 = g_bcc[j], v1 = g_bcc[j + 1];
#pragma unroll
    for (int f = 0; f < NFF; f++) {
        float cf = c[f];
        v0 += cf * g_Wcc[f * NH + j];
        v1 += cf * g_Wcc[f * NH + j + 1];
    }
    float ang = (float)s * expf(-(float)j * 0.0179889460f); // ln(10000)/512
    float sn, cs; sincosf(ang, &sn, &cs);
    v0 += sn; v1 += cs;
    float2* px = (float2*)(g_X + (long)n * NH);
    float2 o = px[j2];
    px[j2] = make_float2(o.x + v0, o.y + v1);
}

// ---------------------------------------------------------------- tf32 tensor-core GEMM
// C[M,N] = scale*(A @ op(B)) + bias
// A:[M,K] row-major. TRB=0: B:[K,N] row-major; TRB=1: B:[N,K] row-major (op=B^T).
// CTA tile 128x64, BK=32, 256 threads (8 warps, 4x2), warp tile 32x32,
// mma.sync.aligned.m16n8k8.row.col.f32.tf32.tf32.f32
#define TBM 128
#define TBN 64
#define TBK 32

template <int TRB>
__global__ __launch_bounds__(256) void k_tgemm(
    const float* __restrict__ A, const float* __restrict__ Bm, float* __restrict__ C,
    int N, int K, long sA, long sB, long sC, const float* __restrict__ bias, float scale) {
    // As: [m][k] stride 36 (frag reads bank-bijective)
    // Bs: TRB=0 -> [k][n] stride 72 ; TRB=1 -> [n][k] stride 36. Both 2304 u32.
    __shared__ u32 As[TBM][TBK + 4];
    __shared__ u32 Bs[2304];

    A  += (long)blockIdx.z * sA;
    Bm += (long)blockIdx.z * sB;
    C  += (long)blockIdx.z * sC;
    int m0 = blockIdx.y * TBM, n0 = blockIdx.x * TBN;
    int t = threadIdx.x;
    int warp = t >> 5, lane = t & 31;
    int wm = (warp >> 1) * 32;          // warp M offset (4 warps)
    int wn = (warp & 1) * 32;           // warp N offset (2 warps)
    int r = lane >> 2, c = lane & 3;    // groupID / threadID_in_group

    float acc[2][4][4];
#pragma unroll
    for (int mt = 0; mt < 2; mt++)
#pragma unroll
        for (int nt = 0; nt < 4; nt++)
#pragma unroll
            for (int i = 0; i < 4; i++) acc[mt][nt][i] = 0.f;

    for (int k0 = 0; k0 < K; k0 += TBK) {
        __syncthreads();
        // ---- load A tile 128x32 -> As[m][k] (tf32)
#pragma unroll
        for (int rr = 0; rr < 4; rr++) {
            int q = t + rr * 256;
            int m = q >> 3, kc = q & 7;
            float4 v = *(const float4*)(A + (long)(m0 + m) * K + k0 + kc * 4);
            u32* dst = &As[m][kc * 4];
            dst[0] = f2tf(v.x); dst[1] = f2tf(v.y);
            dst[2] = f2tf(v.z); dst[3] = f2tf(v.w);
        }
        // ---- load B tile -> Bs (tf32)
        if (TRB == 0) {
#pragma unroll
            for (int rr = 0; rr < 2; rr++) {
                int q = t + rr * 256;
                int k = q >> 4, nc = q & 15;
                float4 v = *(const float4*)(Bm + (long)(k0 + k) * N + n0 + nc * 4);
                u32* dst = &Bs[k * 72 + nc * 4];
                dst[0] = f2tf(v.x); dst[1] = f2tf(v.y);
                dst[2] = f2tf(v.z); dst[3] = f2tf(v.w);
            }
        } else {
#pragma unroll
            for (int rr = 0; rr < 2; rr++) {
                int q = t + rr * 256;
                int n = q >> 3, kc = q & 7;
                float4 v = *(const float4*)(Bm + (long)(n0 + n) * K + k0 + kc * 4);
                u32* dst = &Bs[n * 36 + kc * 4];
                dst[0] = f2tf(v.x); dst[1] = f2tf(v.y);
                dst[2] = f2tf(v.z); dst[3] = f2tf(v.w);
            }
        }
        __syncthreads();
        // ---- 4 k-steps of mma
#pragma unroll
        for (int kb = 0; kb < TBK; kb += 8) {
            u32 a[2][4];
#pragma unroll
            for (int mt = 0; mt < 2; mt++) {
                int row = wm + mt * 16 + r;
                a[mt][0] = As[row][kb + c];
                a[mt][1] = As[row + 8][kb + c];
                a[mt][2] = As[row][kb + c + 4];
                a[mt][3] = As[row + 8][kb + c + 4];
            }
#pragma unroll
            for (int nt = 0; nt < 4; nt++) {
                int col = wn + nt * 8 + r;
                u32 b0, b1;
                if (TRB == 0) {
                    b0 = Bs[(kb + c) * 72 + col];
                    b1 = Bs[(kb + c + 4) * 72 + col];
                } else {
                    b0 = Bs[col * 36 + kb + c];
                    b1 = Bs[col * 36 + kb + c + 4];
                }
#pragma unroll
                for (int mt = 0; mt < 2; mt++) {
                    asm volatile(
                        "mma.sync.aligned.m16n8k8.row.col.f32.tf32.tf32.f32 "
                        "{%0,%1,%2,%3},{%4,%5,%6,%7},{%8,%9},{%0,%1,%2,%3};"
                        : "+f"(acc[mt][nt][0]), "+f"(acc[mt][nt][1]),
                          "+f"(acc[mt][nt][2]), "+f"(acc[mt][nt][3])
                        : "r"(a[mt][0]), "r"(a[mt][1]), "r"(a[mt][2]), "r"(a[mt][3]),
                          "r"(b0), "r"(b1));
                }
            }
        }
    }
    // ---- epilogue
#pragma unroll
    for (int mt = 0; mt < 2; mt++) {
#pragma unroll
        for (int nt = 0; nt < 4; nt++) {
            int row = m0 + wm + mt * 16 + r;
            int col = n0 + wn + nt * 8 + c * 2;
            float bb0 = 0.f, bb1 = 0.f;
            if (bias) { bb0 = __ldg(bias + col); bb1 = __ldg(bias + col + 1); }
            float2 lo = make_float2(acc[mt][nt][0] * scale + bb0,
                                    acc[mt][nt][1] * scale + bb1);
            float2 hi = make_float2(acc[mt][nt][2] * scale + bb0,
                                    acc[mt][nt][3] * scale + bb1);
            *(float2*)(C + (long)row * N + col) = lo;
            *(float2*)(C + (long)(row + 8) * N + col) = hi;
        }
    }
}

// ---------------------------------------------------------------- softmax over q (axis=1)
__global__ void k_softmax(float* __restrict__ P) {
    int tid = blockIdx.x * 256 + threadIdx.x;       // 32768 = b*512+k
    int b = tid >> 9, k = tid & 511;
    float* p = P + (long)b * (NS * NS) + k;
    float m = -1e30f;
    for (int q = 0; q < NS; q++) m = fmaxf(m, p[q * NS]);
    float s = 0.f;
    for (int q = 0; q < NS; q++) { float e = __expf(p[q * NS] - m); s += e; p[q * NS] = e; }
    float inv = 1.f / s;
    for (int q = 0; q < NS; q++) p[q * NS] *= inv;
}

// ---------------------------------------------------------------- z[b,s,:] -> Zt[(s,b),:]
__global__ void k_perm(const float4* __restrict__ in, float4* __restrict__ out) {
    long tid = (long)blockIdx.x * 256 + threadIdx.x;   // BS*128
    int row = (int)(tid >> 7), c = (int)(tid & 127);
    int s = row >> 6, b = row & 63;
    out[(long)row * 128 + c] = in[((long)b * NS + s) * 128 + c];
}

__global__ void k_zero(float* p, int n) {
    int i = blockIdx.x * 256 + threadIdx.x;
    if (i < n) p[i] = 0.f;
}

// ---------------------------------------------------------------- grid barrier
__device__ __forceinline__ void gbar() {
    __syncthreads();
    if (threadIdx.x == 0) {
        unsigned gen = g_phase;
        __threadfence();
        if (atomicAdd(&g_cnt, 1u) == gridDim.x - 1u) {
            g_cnt = 0;
            __threadfence();
            g_phase = gen + 1u;
        } else {
            while (g_phase == gen) { }
            __threadfence();
        }
    }
    __syncthreads();
}

// ---------------------------------------------------------------- persistent GRU layer
__global__ __launch_bounds__(256) void k_gru(const float* __restrict__ GI,
                                             const float* __restrict__ Wh,
                                             const float* __restrict__ bh,
                                             float* __restrict__ Hout) {
    __shared__ float ws[12][516];
    int t = threadIdx.x;
    int u0 = blockIdx.x * 4;
    for (int r = 0; r < 12; r++) {
        int gate = r >> 2, i = r & 3;
        const float* src = Wh + (long)(gate * NA + u0 + i) * NA;
        for (int k = t; k < NA; k += 256) ws[r][k] = src[k];
    }
    __syncthreads();
    int b = t >> 2, jg = t & 3;
    int u = u0 + jg;
    float bhr = bh[u], bhz = bh[NA + u], bhn = bh[2 * NA + u];

    for (int s = 0; s < NS; s++) {
        const float* hc = g_h[s & 1];
        float* hn = g_h[(s & 1) ^ 1];
        const float4* hv = (const float4*)(hc + b * NA);
        ull a0 = 0, a1 = 0, a2 = 0, a3 = 0, a4 = 0, a5 = 0;
#pragma unroll 4
        for (int k = 0; k < 128; k++) {
            float4 h4 = __ldcg(hv + k);
            ull hx = pk(h4.x, h4.y), hy = pk(h4.z, h4.w);
            ulonglong2 wr = *(const ulonglong2*)&ws[jg][k * 4];
            ulonglong2 wz = *(const ulonglong2*)&ws[4 + jg][k * 4];
            ulonglong2 wn = *(const ulonglong2*)&ws[8 + jg][k * 4];
            fma2(a0, hx, wr.x); fma2(a1, hy, wr.y);
            fma2(a2, hx, wz.x); fma2(a3, hy, wz.y);
            fma2(a4, hx, wn.x); fma2(a5, hy, wn.y);
        }
        float2 r0 = upk(a0), r1 = upk(a1);
        float2 z0 = upk(a2), z1 = upk(a3);
        float2 n0 = upk(a4), n1 = upk(a5);
        float ar = r0.x + r0.y + r1.x + r1.y;
        float az = z0.x + z0.y + z1.x + z1.y;
        float an = n0.x + n0.y + n1.x + n1.y;

        long m = (long)s * NB + b;
        const float* gi = GI + m * (3 * NA);
        float gr = __ldg(gi + u), gz = __ldg(gi + NA + u), gn = __ldg(gi + 2 * NA + u);
        float r = sigm(gr + ar + bhr);
        float z = sigm(gz + az + bhz);
        float n = tanhf(gn + r * (an + bhn));
        float hp = __ldcg(&hc[b * NA + u]);
        float hval = (1.f - z) * n + z * hp;
        hn[b * NA + u] = hval;
        Hout[m * NA + u] = hval;
        __threadfence();
        gbar();
    }
}

// ---------------------------------------------------------------- head
__global__ void k_head(const float* __restrict__ Hs, const float* __restrict__ Wf,
                       const float* __restrict__ bf, float* __restrict__ out) {
    int warp = (blockIdx.x * 256 + threadIdx.x) >> 5;   // row (s,b)
    int lane = threadIdx.x & 31;
    const float* row = Hs + (long)warp * NA;
    float s = 0.f;
#pragma unroll
    for (int i = 0; i < 16; i++) s += row[lane + i * 32] * __ldg(&Wf[lane + i * 32]);
#pragma unroll
    for (int o = 16; o; o >>= 1) s += __shfl_xor_sync(0xffffffffu, s, o);
    if (lane == 0) {
        int ss = warp >> 6, b = warp & 63;
        out[b * NS + ss] = sigm(s + __ldg(bf));
    }
}

// ---------------------------------------------------------------- launch
extern "C" void kernel_launch(void* const* d_in, const int* in_sizes, int n_in,
                              void* d_out, int out_size) {
    const int*   cate  = (const int*)d_in[0];
    const float* cont  = (const float*)d_in[1];
    const float* emb   = (const float*)d_in[4];
    const float* Wcont = (const float*)d_in[5];
    const float* bcont = (const float*)d_in[6];
    const float* Wcomb = (const float*)d_in[7];
    const float* bcomb = (const float*)d_in[8];
    const float* Wq    = (const float*)d_in[9];
    const float* Wk    = (const float*)d_in[10];
    const float* Wv    = (const float*)d_in[11];
    const float* Wi    = (const float*)d_in[12];
    const float* Wh    = (const float*)d_in[13];
    const float* bi    = (const float*)d_in[14];
    const float* bh    = (const float*)d_in[15];
    const float* Wfin  = (const float*)d_in[16];
    const float* bfin  = (const float*)d_in[17];
    float* out = (float*)d_out;

    float *CE, *X, *Q, *K, *V, *GI, *H0;
    cudaGetSymbolAddress((void**)&CE, g_CE);
    cudaGetSymbolAddress((void**)&X,  g_X);
    cudaGetSymbolAddress((void**)&Q,  g_Q);
    cudaGetSymbolAddress((void**)&K,  g_K);
    cudaGetSymbolAddress((void**)&V,  g_V);
    cudaGetSymbolAddress((void**)&GI, g_GI);
    cudaGetSymbolAddress((void**)&H0, g_h);

    const long SB2 = (long)NS * NS;   // 262144
    const float iscl = 0.0441941738241592f; // 1/sqrt(512)

    k_prep<<<2, 256>>>(Wcont, bcont, Wcomb, bcomb);
    k_gather<<<BS * NH / 256, 256>>>(cate, emb);
    // x = CE @ Wcomb[0:512]
    k_tgemm<0><<<dim3(8, 256, 1), 256>>>(CE, Wcomb, X, NH, NH, 0, 0, 0, nullptr, 1.f);
    k_extras<<<BS, 256>>>(cont);
    // QKV
    k_tgemm<0><<<dim3(8, 256, 1), 256>>>(X, Wq, Q, NA, NH, 0, 0, 0, nullptr, 1.f);
    k_tgemm<0><<<dim3(8, 256, 1), 256>>>(X, Wk, K, NA, NH, 0, 0, 0, nullptr, 1.f);
    k_tgemm<0><<<dim3(8, 256, 1), 256>>>(X, Wv, V, NA, NH, 0, 0, 0, nullptr, 1.f);
    // scores = Q @ K^T / sqrt(A)   (batched over b)
    k_tgemm<1><<<dim3(8, 4, 64), 256>>>(Q, K, CE, NS, NA, SB2, SB2, SB2, nullptr, iscl);
    k_softmax<<<128, 256>>>(CE);
    // z = P @ V
    k_tgemm<0><<<dim3(8, 4, 64), 256>>>(CE, V, X, NA, NS, SB2, SB2, SB2, nullptr, 1.f);
    // Zt[(s,b),:] = z[b,s,:]
    k_perm<<<BS * 128 / 256, 256>>>((const float4*)X, (float4*)Q);
    // layer 0
    k_zero<<<128, 256>>>(H0, NB * NA);
    k_tgemm<1><<<dim3(24, 256, 1), 256>>>(Q, Wi, GI, 3 * NA, NA, 0, 0, 0, bi, 1.f);
    k_gru<<<128, 256>>>(GI, Wh, bh, K);
    // layer 1
    k_zero<<<128, 256>>>(H0, NB * NA);
    k_tgemm<1><<<dim3(24, 256, 1), 256>>>(K, Wi + 3 * NA * NA, GI, 3 * NA, NA, 0, 0, 0,
                                          bi + 3 * NA, 1.f);
    k_gru<<<128, 256>>>(GI, Wh + 3 * NA * NA, bh + 3 * NA, V);
    // head
    k_head<<<BS / 8, 256>>>(V, Wfin, bfin, out);
}

// round 4
// speedup vs baseline: 1.7233x; 1.5610x over previous
#include <cuda_runtime.h>
#include <math.h>

typedef unsigned long long ull;
typedef unsigned int u32;

// ---------------------------------------------------------------- constants
#define NB   64
#define NS   512
#define NH   512
#define NA   512
#define NCC  4
#define NV   1000
#define NED  128
#define NFF  6
#define BS   32768          // NB*NS

// ---------------------------------------------------------------- scratch
__device__ float g_CE[BS * NH];       // gathered embeddings; reused as scores
__device__ float g_X [BS * NH];       // x; reused as z
__device__ float g_Q [BS * NA];       // Q; reused as Zt
__device__ float g_K [BS * NA];       // K; reused as GRU layer-0 output
__device__ float g_V [BS * NA];       // V; reused as GRU layer-1 output
__device__ float g_GI[BS * 3 * NA];   // GRU input gates (per layer)
__device__ float g_h [2][NB * NA];    // double-buffered hidden state
__device__ float g_Wcc[NFF * NH];
__device__ float g_bcc[NH];
__device__ unsigned g_cnt = 0;
__device__ volatile unsigned g_phase = 0;

// ---------------------------------------------------------------- helpers
__device__ __forceinline__ ull pk(float a, float b) {
    ull r; asm("mov.b64 %0,{%1,%2};" : "=l"(r) : "f"(a), "f"(b)); return r;
}
__device__ __forceinline__ void fma2(ull& d, ull a, ull b) {
    asm("fma.rn.f32x2 %0,%1,%2,%0;" : "+l"(d) : "l"(a), "l"(b));
}
__device__ __forceinline__ float2 upk(ull v) {
    float2 f; asm("mov.b64 {%0,%1},%2;" : "=f"(f.x), "=f"(f.y) : "l"(v)); return f;
}
__device__ __forceinline__ float sigm(float x) { return 1.f / (1.f + expf(-x)); }
__device__ __forceinline__ u32 f2tf(float x) {
    u32 r; asm("cvt.rna.tf32.f32 %0,%1;" : "=r"(r) : "f"(x)); return r;
}

// ---------------------------------------------------------------- prep
__global__ void k_prep(const float* __restrict__ Wcont, const float* __restrict__ bcont,
                       const float* __restrict__ Wcomb, const float* __restrict__ bcomb) {
    int j = blockIdx.x * 256 + threadIdx.x;
    if (j >= NH) return;
    float acc[NFF];
#pragma unroll
    for (int f = 0; f < NFF; f++) acc[f] = 0.f;
    float bacc = bcomb[j];
    for (int m = 0; m < NH; m++) {
        float w2 = Wcomb[(NH + m) * NH + j];
        bacc += bcont[m] * w2;
#pragma unroll
        for (int f = 0; f < NFF; f++) acc[f] += Wcont[f * NH + m] * w2;
    }
#pragma unroll
    for (int f = 0; f < NFF; f++) g_Wcc[f * NH + j] = acc[f];
    g_bcc[j] = bacc;
}

// ---------------------------------------------------------------- gather
__global__ void k_gather(const int* __restrict__ cate, const float* __restrict__ emb) {
    long i = (long)blockIdx.x * 256 + threadIdx.x;
    int n = (int)(i >> 9);
    int col = (int)(i & 511);
    int c = col >> 7, e = col & 127;
    int idx = cate[n * NCC + c];
    g_CE[i] = emb[((long)c * NV + idx) * NED + e];
}

// ---------------------------------------------------------------- extras
__global__ void k_extras(const float* __restrict__ cont) {
    int n = blockIdx.x;
    int j2 = threadIdx.x;
    __shared__ float c[NFF];
    if (threadIdx.x < NFF) c[threadIdx.x] = cont[n * NFF + threadIdx.x];
    __syncthreads();
    int s = n & (NS - 1);
    int j = j2 * 2;
    float v0 = g_bcc[j], v1 = g_bcc[j + 1];
#pragma unroll
    for (int f = 0; f < NFF; f++) {
        float cf = c[f];
        v0 += cf * g_Wcc[f * NH + j];
        v1 += cf * g_Wcc[f * NH + j + 1];
    }
    float ang = (float)s * expf(-(float)j * 0.0179889460f); // ln(10000)/512
    float sn, cs; sincosf(ang, &sn, &cs);
    v0 += sn; v1 += cs;
    float2* px = (float2*)(g_X + (long)n * NH);
    float2 o = px[j2];
    px[j2] = make_float2(o.x + v0, o.y + v1);
}

// ---------------------------------------------------------------- tf32 tensor-core GEMM
#define TBM 128
#define TBN 64
#define TBK 32

template <int TRB>
__global__ __launch_bounds__(256) void k_tgemm(
    const float* __restrict__ A, const float* __restrict__ Bm, float* __restrict__ C,
    int N, int K, long sA, long sB, long sC, const float* __restrict__ bias, float scale) {
    __shared__ u32 As[TBM][TBK + 4];
    __shared__ u32 Bs[2304];

    A  += (long)blockIdx.z * sA;
    Bm += (long)blockIdx.z * sB;
    C  += (long)blockIdx.z * sC;
    int m0 = blockIdx.y * TBM, n0 = blockIdx.x * TBN;
    int t = threadIdx.x;
    int warp = t >> 5, lane = t & 31;
    int wm = (warp >> 1) * 32;
    int wn = (warp & 1) * 32;
    int r = lane >> 2, c = lane & 3;

    float acc[2][4][4];
#pragma unroll
    for (int mt = 0; mt < 2; mt++)
#pragma unroll
        for (int nt = 0; nt < 4; nt++)
#pragma unroll
            for (int i = 0; i < 4; i++) acc[mt][nt][i] = 0.f;

    for (int k0 = 0; k0 < K; k0 += TBK) {
        __syncthreads();
#pragma unroll
        for (int rr = 0; rr < 4; rr++) {
            int q = t + rr * 256;
            int m = q >> 3, kc = q & 7;
            float4 v = *(const float4*)(A + (long)(m0 + m) * K + k0 + kc * 4);
            u32* dst = &As[m][kc * 4];
            dst[0] = f2tf(v.x); dst[1] = f2tf(v.y);
            dst[2] = f2tf(v.z); dst[3] = f2tf(v.w);
        }
        if (TRB == 0) {
#pragma unroll
            for (int rr = 0; rr < 2; rr++) {
                int q = t + rr * 256;
                int k = q >> 4, nc = q & 15;
                float4 v = *(const float4*)(Bm + (long)(k0 + k) * N + n0 + nc * 4);
                u32* dst = &Bs[k * 72 + nc * 4];
                dst[0] = f2tf(v.x); dst[1] = f2tf(v.y);
                dst[2] = f2tf(v.z); dst[3] = f2tf(v.w);
            }
        } else {
#pragma unroll
            for (int rr = 0; rr < 2; rr++) {
                int q = t + rr * 256;
                int n = q >> 3, kc = q & 7;
                float4 v = *(const float4*)(Bm + (long)(n0 + n) * K + k0 + kc * 4);
                u32* dst = &Bs[n * 36 + kc * 4];
                dst[0] = f2tf(v.x); dst[1] = f2tf(v.y);
                dst[2] = f2tf(v.z); dst[3] = f2tf(v.w);
            }
        }
        __syncthreads();
#pragma unroll
        for (int kb = 0; kb < TBK; kb += 8) {
            u32 a[2][4];
#pragma unroll
            for (int mt = 0; mt < 2; mt++) {
                int row = wm + mt * 16 + r;
                a[mt][0] = As[row][kb + c];
                a[mt][1] = As[row + 8][kb + c];
                a[mt][2] = As[row][kb + c + 4];
                a[mt][3] = As[row + 8][kb + c + 4];
            }
#pragma unroll
            for (int nt = 0; nt < 4; nt++) {
                int col = wn + nt * 8 + r;
                u32 b0, b1;
                if (TRB == 0) {
                    b0 = Bs[(kb + c) * 72 + col];
                    b1 = Bs[(kb + c + 4) * 72 + col];
                } else {
                    b0 = Bs[col * 36 + kb + c];
                    b1 = Bs[col * 36 + kb + c + 4];
                }
#pragma unroll
                for (int mt = 0; mt < 2; mt++) {
                    asm volatile(
                        "mma.sync.aligned.m16n8k8.row.col.f32.tf32.tf32.f32 "
                        "{%0,%1,%2,%3},{%4,%5,%6,%7},{%8,%9},{%0,%1,%2,%3};"
                        : "+f"(acc[mt][nt][0]), "+f"(acc[mt][nt][1]),
                          "+f"(acc[mt][nt][2]), "+f"(acc[mt][nt][3])
                        : "r"(a[mt][0]), "r"(a[mt][1]), "r"(a[mt][2]), "r"(a[mt][3]),
                          "r"(b0), "r"(b1));
                }
            }
        }
    }
#pragma unroll
    for (int mt = 0; mt < 2; mt++) {
#pragma unroll
        for (int nt = 0; nt < 4; nt++) {
            int row = m0 + wm + mt * 16 + r;
            int col = n0 + wn + nt * 8 + c * 2;
            float bb0 = 0.f, bb1 = 0.f;
            if (bias) { bb0 = __ldg(bias + col); bb1 = __ldg(bias + col + 1); }
            float2 lo = make_float2(acc[mt][nt][0] * scale + bb0,
                                    acc[mt][nt][1] * scale + bb1);
            float2 hi = make_float2(acc[mt][nt][2] * scale + bb0,
                                    acc[mt][nt][3] * scale + bb1);
            *(float2*)(C + (long)row * N + col) = lo;
            *(float2*)(C + (long)(row + 8) * N + col) = hi;
        }
    }
}

// ---------------------------------------------------------------- softmax over q (axis=1)
__global__ void k_softmax(float* __restrict__ P) {
    int tid = blockIdx.x * 256 + threadIdx.x;
    int b = tid >> 9, k = tid & 511;
    float* p = P + (long)b * (NS * NS) + k;
    float m = -1e30f;
    for (int q = 0; q < NS; q++) m = fmaxf(m, p[q * NS]);
    float s = 0.f;
    for (int q = 0; q < NS; q++) { float e = __expf(p[q * NS] - m); s += e; p[q * NS] = e; }
    float inv = 1.f / s;
    for (int q = 0; q < NS; q++) p[q * NS] *= inv;
}

// ---------------------------------------------------------------- z[b,s,:] -> Zt[(s,b),:]
__global__ void k_perm(const float4* __restrict__ in, float4* __restrict__ out) {
    long tid = (long)blockIdx.x * 256 + threadIdx.x;
    int row = (int)(tid >> 7), c = (int)(tid & 127);
    int s = row >> 6, b = row & 63;
    out[(long)row * 128 + c] = in[((long)b * NS + s) * 128 + c];
}

// ---------------------------------------------------------------- grid barrier (cg pattern)
__device__ __forceinline__ void gbar() {
    __syncthreads();
    if (threadIdx.x == 0) {
        unsigned gen = g_phase;
        __threadfence();
        if (atomicAdd(&g_cnt, 1u) == gridDim.x - 1u) {
            g_cnt = 0;
            __threadfence();
            g_phase = gen + 1u;
        } else {
            while (g_phase == gen) { }
            __threadfence();
        }
    }
    __syncthreads();
}

// ---------------------------------------------------------------- persistent GRU layer
// 128 CTAs x 256 threads. CTA owns 4 units (all 3 gates); Wh slice + full h_prev in SMEM.
// Dynamic smem: ws[12][516] + hs[64][516] = 156,864 B.
#define HPAD 516
#define GRU_SMEM ((12 + 64) * HPAD * 4)

__global__ __launch_bounds__(256) void k_gru(const float* __restrict__ GI,
                                             const float* __restrict__ Wh,
                                             const float* __restrict__ bh,
                                             float* __restrict__ Hout) {
    extern __shared__ float sm[];
    float* ws = sm;                 // 12 rows of Wh
    float* hs = sm + 12 * HPAD;     // staged h_prev [64][516]
    int t = threadIdx.x;
    int u0 = blockIdx.x * 4;
    for (int rr = 0; rr < 12; rr++) {
        int gate = rr >> 2, i = rr & 3;
        const float* src = Wh + (long)(gate * NA + u0 + i) * NA;
        for (int k = t; k < NA; k += 256) ws[rr * HPAD + k] = src[k];
    }
    int b = t >> 2, jg = t & 3;
    int u = u0 + jg;
    float bhr = bh[u], bhz = bh[NA + u], bhn = bh[2 * NA + u];
    const float* wrp = ws + jg * HPAD;
    const float* wzp = ws + (4 + jg) * HPAD;
    const float* wnp = ws + (8 + jg) * HPAD;
    __syncthreads();

    for (int s = 0; s < NS; s++) {
        // GI prefetch (independent of barrier/staging)
        long m = (long)s * NB + b;
        const float* gi = GI + m * (3 * NA);
        float gr = __ldg(gi + u), gz = __ldg(gi + NA + u), gn = __ldg(gi + 2 * NA + u);

        // stage h_prev into SMEM (coalesced float4, L2-fresh via .cg)
        if (s == 0) {
            float4 zz = make_float4(0.f, 0.f, 0.f, 0.f);
#pragma unroll
            for (int i = 0; i < 32; i++) {
                int g = t + i * 256;
                *(float4*)&hs[(g >> 7) * HPAD + (g & 127) * 4] = zz;
            }
        } else {
            const float4* hg = (const float4*)g_h[s & 1];
#pragma unroll
            for (int i = 0; i < 32; i++) {
                int g = t + i * 256;
                float4 v = __ldcg(hg + g);
                *(float4*)&hs[(g >> 7) * HPAD + (g & 127) * 4] = v;
            }
        }
        __syncthreads();

        const float* hb = hs + b * HPAD;
        ull a0 = 0, a1 = 0, a2 = 0, a3 = 0, a4 = 0, a5 = 0;
#pragma unroll 8
        for (int k = 0; k < 128; k++) {
            float4 h4 = *(const float4*)(hb + 4 * k);
            ull hx = pk(h4.x, h4.y), hy = pk(h4.z, h4.w);
            ulonglong2 wr = *(const ulonglong2*)(wrp + 4 * k);
            ulonglong2 wz = *(const ulonglong2*)(wzp + 4 * k);
            ulonglong2 wn = *(const ulonglong2*)(wnp + 4 * k);
            fma2(a0, hx, wr.x); fma2(a1, hy, wr.y);
            fma2(a2, hx, wz.x); fma2(a3, hy, wz.y);
            fma2(a4, hx, wn.x); fma2(a5, hy, wn.y);
        }
        float2 r0 = upk(a0), r1 = upk(a1);
        float2 z0 = upk(a2), z1 = upk(a3);
        float2 n0 = upk(a4), n1 = upk(a5);
        float ar = r0.x + r0.y + r1.x + r1.y;
        float az = z0.x + z0.y + z1.x + z1.y;
        float an = n0.x + n0.y + n1.x + n1.y;

        float r = sigm(gr + ar + bhr);
        float z = sigm(gz + az + bhz);
        float n = tanhf(gn + r * (an + bhn));
        float hp = hb[u];
        float hval = (1.f - z) * n + z * hp;
        g_h[(s & 1) ^ 1][b * NA + u] = hval;
        Hout[m * NA + u] = hval;
        gbar();
    }
}

// ---------------------------------------------------------------- head
__global__ void k_head(const float* __restrict__ Hs, const float* __restrict__ Wf,
                       const float* __restrict__ bf, float* __restrict__ out) {
    int warp = (blockIdx.x * 256 + threadIdx.x) >> 5;
    int lane = threadIdx.x & 31;
    const float* row = Hs + (long)warp * NA;
    float s = 0.f;
#pragma unroll
    for (int i = 0; i < 16; i++) s += row[lane + i * 32] * __ldg(&Wf[lane + i * 32]);
#pragma unroll
    for (int o = 16; o; o >>= 1) s += __shfl_xor_sync(0xffffffffu, s, o);
    if (lane == 0) {
        int ss = warp >> 6, b = warp & 63;
        out[b * NS + ss] = sigm(s + __ldg(bf));
    }
}

// ---------------------------------------------------------------- launch
extern "C" void kernel_launch(void* const* d_in, const int* in_sizes, int n_in,
                              void* d_out, int out_size) {
    const int*   cate  = (const int*)d_in[0];
    const float* cont  = (const float*)d_in[1];
    const float* emb   = (const float*)d_in[4];
    const float* Wcont = (const float*)d_in[5];
    const float* bcont = (const float*)d_in[6];
    const float* Wcomb = (const float*)d_in[7];
    const float* bcomb = (const float*)d_in[8];
    const float* Wq    = (const float*)d_in[9];
    const float* Wk    = (const float*)d_in[10];
    const float* Wv    = (const float*)d_in[11];
    const float* Wi    = (const float*)d_in[12];
    const float* Wh    = (const float*)d_in[13];
    const float* bi    = (const float*)d_in[14];
    const float* bh    = (const float*)d_in[15];
    const float* Wfin  = (const float*)d_in[16];
    const float* bfin  = (const float*)d_in[17];
    float* out = (float*)d_out;

    float *CE, *X, *Q, *K, *V, *GI;
    cudaGetSymbolAddress((void**)&CE, g_CE);
    cudaGetSymbolAddress((void**)&X,  g_X);
    cudaGetSymbolAddress((void**)&Q,  g_Q);
    cudaGetSymbolAddress((void**)&K,  g_K);
    cudaGetSymbolAddress((void**)&V,  g_V);
    cudaGetSymbolAddress((void**)&GI, g_GI);

    cudaFuncSetAttribute(k_gru, cudaFuncAttributeMaxDynamicSharedMemorySize, GRU_SMEM);

    const long SB2 = (long)NS * NS;
    const float iscl = 0.0441941738241592f; // 1/sqrt(512)

    k_prep<<<2, 256>>>(Wcont, bcont, Wcomb, bcomb);
    k_gather<<<BS * NH / 256, 256>>>(cate, emb);
    k_tgemm<0><<<dim3(8, 256, 1), 256>>>(CE, Wcomb, X, NH, NH, 0, 0, 0, nullptr, 1.f);
    k_extras<<<BS, 256>>>(cont);
    k_tgemm<0><<<dim3(8, 256, 1), 256>>>(X, Wq, Q, NA, NH, 0, 0, 0, nullptr, 1.f);
    k_tgemm<0><<<dim3(8, 256, 1), 256>>>(X, Wk, K, NA, NH, 0, 0, 0, nullptr, 1.f);
    k_tgemm<0><<<dim3(8, 256, 1), 256>>>(X, Wv, V, NA, NH, 0, 0, 0, nullptr, 1.f);
    k_tgemm<1><<<dim3(8, 4, 64), 256>>>(Q, K, CE, NS, NA, SB2, SB2, SB2, nullptr, iscl);
    k_softmax<<<128, 256>>>(CE);
    k_tgemm<0><<<dim3(8, 4, 64), 256>>>(CE, V, X, NA, NS, SB2, SB2, SB2, nullptr, 1.f);
    k_perm<<<BS * 128 / 256, 256>>>((const float4*)X, (float4*)Q);
    // layer 0
    k_tgemm<1><<<dim3(24, 256, 1), 256>>>(Q, Wi, GI, 3 * NA, NA, 0, 0, 0, bi, 1.f);
    k_gru<<<128, 256, GRU_SMEM>>>(GI, Wh, bh, K);
    // layer 1
    k_tgemm<1><<<dim3(24, 256, 1), 256>>>(K, Wi + 3 * NA * NA, GI, 3 * NA, NA, 0, 0, 0,
                                          bi + 3 * NA, 1.f);
    k_gru<<<128, 256, GRU_SMEM>>>(GI, Wh + 3 * NA * NA, bh + 3 * NA, V);
    // head
    k_head<<<BS / 8, 256>>>(V, Wfin, bfin, out);
}

// round 6
// speedup vs baseline: 2.3888x; 1.3862x over previous
#include <cuda_runtime.h>
#include <math.h>

typedef unsigned long long ull;
typedef unsigned int u32;

// ---------------------------------------------------------------- constants
#define NB   64
#define NS   512
#define NH   512
#define NA   512
#define NCC  4
#define NV   1000
#define NED  128
#define NFF  6
#define BS   32768          // NB*NS

// ---------------------------------------------------------------- scratch
__device__ float g_CE[BS * NH];       // gathered embeddings; reused as scores
__device__ float g_X [BS * NH];       // x; reused as z
__device__ float g_Q [BS * NA];       // Q; reused as Zt
__device__ float g_K [BS * NA];       // K; reused as GRU layer-0 output
__device__ float g_V [BS * NA];       // V; reused as GRU layer-1 output
__device__ float g_GI[BS * 3 * NA];   // GRU input gates (per layer)
__device__ float g_h [2][NB * NA];    // double-buffered hidden state
__device__ float g_Wcc[NFF * NH];
__device__ float g_bcc[NH];
__device__ unsigned g_cnt = 0;
__device__ volatile unsigned g_phase = 0;

// ---------------------------------------------------------------- helpers
__device__ __forceinline__ float sigm(float x) { return 1.f / (1.f + expf(-x)); }
__device__ __forceinline__ u32 f2tf(float x) {
    u32 r; asm("cvt.rna.tf32.f32 %0,%1;" : "=r"(r) : "f"(x)); return r;
}

// ---------------------------------------------------------------- prep
__global__ void k_prep(const float* __restrict__ Wcont, const float* __restrict__ bcont,
                       const float* __restrict__ Wcomb, const float* __restrict__ bcomb) {
    int j = blockIdx.x * 256 + threadIdx.x;
    if (j >= NH) return;
    float acc[NFF];
#pragma unroll
    for (int f = 0; f < NFF; f++) acc[f] = 0.f;
    float bacc = bcomb[j];
    for (int m = 0; m < NH; m++) {
        float w2 = Wcomb[(NH + m) * NH + j];
        bacc += bcont[m] * w2;
#pragma unroll
        for (int f = 0; f < NFF; f++) acc[f] += Wcont[f * NH + m] * w2;
    }
#pragma unroll
    for (int f = 0; f < NFF; f++) g_Wcc[f * NH + j] = acc[f];
    g_bcc[j] = bacc;
}

// ---------------------------------------------------------------- gather
__global__ void k_gather(const int* __restrict__ cate, const float* __restrict__ emb) {
    long i = (long)blockIdx.x * 256 + threadIdx.x;
    int n = (int)(i >> 9);
    int col = (int)(i & 511);
    int c = col >> 7, e = col & 127;
    int idx = cate[n * NCC + c];
    g_CE[i] = emb[((long)c * NV + idx) * NED + e];
}

// ---------------------------------------------------------------- extras
__global__ void k_extras(const float* __restrict__ cont) {
    int n = blockIdx.x;
    int j2 = threadIdx.x;
    __shared__ float c[NFF];
    if (threadIdx.x < NFF) c[threadIdx.x] = cont[n * NFF + threadIdx.x];
    __syncthreads();
    int s = n & (NS - 1);
    int j = j2 * 2;
    float v0 = g_bcc[j], v1 = g_bcc[j + 1];
#pragma unroll
    for (int f = 0; f < NFF; f++) {
        float cf = c[f];
        v0 += cf * g_Wcc[f * NH + j];
        v1 += cf * g_Wcc[f * NH + j + 1];
    }
    float ang = (float)s * expf(-(float)j * 0.0179889460f); // ln(10000)/512
    float sn, cs; sincosf(ang, &sn, &cs);
    v0 += sn; v1 += cs;
    float2* px = (float2*)(g_X + (long)n * NH);
    float2 o = px[j2];
    px[j2] = make_float2(o.x + v0, o.y + v1);
}

// ---------------------------------------------------------------- tf32 tensor-core GEMM
#define TBM 128
#define TBN 64
#define TBK 32

template <int TRB>
__global__ __launch_bounds__(256) void k_tgemm(
    const float* __restrict__ A, const float* __restrict__ Bm, float* __restrict__ C,
    int N, int K, long sA, long sB, long sC, const float* __restrict__ bias, float scale) {
    __shared__ u32 As[TBM][TBK + 4];
    __shared__ u32 Bs[2304];

    A  += (long)blockIdx.z * sA;
    Bm += (long)blockIdx.z * sB;
    C  += (long)blockIdx.z * sC;
    int m0 = blockIdx.y * TBM, n0 = blockIdx.x * TBN;
    int t = threadIdx.x;
    int warp = t >> 5, lane = t & 31;
    int wm = (warp >> 1) * 32;
    int wn = (warp & 1) * 32;
    int r = lane >> 2, c = lane & 3;

    float acc[2][4][4];
#pragma unroll
    for (int mt = 0; mt < 2; mt++)
#pragma unroll
        for (int nt = 0; nt < 4; nt++)
#pragma unroll
            for (int i = 0; i < 4; i++) acc[mt][nt][i] = 0.f;

    for (int k0 = 0; k0 < K; k0 += TBK) {
        __syncthreads();
#pragma unroll
        for (int rr = 0; rr < 4; rr++) {
            int q = t + rr * 256;
            int m = q >> 3, kc = q & 7;
            float4 v = *(const float4*)(A + (long)(m0 + m) * K + k0 + kc * 4);
            u32* dst = &As[m][kc * 4];
            dst[0] = f2tf(v.x); dst[1] = f2tf(v.y);
            dst[2] = f2tf(v.z); dst[3] = f2tf(v.w);
        }
        if (TRB == 0) {
#pragma unroll
            for (int rr = 0; rr < 2; rr++) {
                int q = t + rr * 256;
                int k = q >> 4, nc = q & 15;
                float4 v = *(const float4*)(Bm + (long)(k0 + k) * N + n0 + nc * 4);
                u32* dst = &Bs[k * 72 + nc * 4];
                dst[0] = f2tf(v.x); dst[1] = f2tf(v.y);
                dst[2] = f2tf(v.z); dst[3] = f2tf(v.w);
            }
        } else {
#pragma unroll
            for (int rr = 0; rr < 2; rr++) {
                int q = t + rr * 256;
                int n = q >> 3, kc = q & 7;
                float4 v = *(const float4*)(Bm + (long)(n0 + n) * K + k0 + kc * 4);
                u32* dst = &Bs[n * 36 + kc * 4];
                dst[0] = f2tf(v.x); dst[1] = f2tf(v.y);
                dst[2] = f2tf(v.z); dst[3] = f2tf(v.w);
            }
        }
        __syncthreads();
#pragma unroll
        for (int kb = 0; kb < TBK; kb += 8) {
            u32 a[2][4];
#pragma unroll
            for (int mt = 0; mt < 2; mt++) {
                int row = wm + mt * 16 + r;
                a[mt][0] = As[row][kb + c];
                a[mt][1] = As[row + 8][kb + c];
                a[mt][2] = As[row][kb + c + 4];
                a[mt][3] = As[row + 8][kb + c + 4];
            }
#pragma unroll
            for (int nt = 0; nt < 4; nt++) {
                int col = wn + nt * 8 + r;
                u32 b0, b1;
                if (TRB == 0) {
                    b0 = Bs[(kb + c) * 72 + col];
                    b1 = Bs[(kb + c + 4) * 72 + col];
                } else {
                    b0 = Bs[col * 36 + kb + c];
                    b1 = Bs[col * 36 + kb + c + 4];
                }
#pragma unroll
                for (int mt = 0; mt < 2; mt++) {
                    asm volatile(
                        "mma.sync.aligned.m16n8k8.row.col.f32.tf32.tf32.f32 "
                        "{%0,%1,%2,%3},{%4,%5,%6,%7},{%8,%9},{%0,%1,%2,%3};"
                        : "+f"(acc[mt][nt][0]), "+f"(acc[mt][nt][1]),
                          "+f"(acc[mt][nt][2]), "+f"(acc[mt][nt][3])
                        : "r"(a[mt][0]), "r"(a[mt][1]), "r"(a[mt][2]), "r"(a[mt][3]),
                          "r"(b0), "r"(b1));
                }
            }
        }
    }
#pragma unroll
    for (int mt = 0; mt < 2; mt++) {
#pragma unroll
        for (int nt = 0; nt < 4; nt++) {
            int row = m0 + wm + mt * 16 + r;
            int col = n0 + wn + nt * 8 + c * 2;
            float bb0 = 0.f, bb1 = 0.f;
            if (bias) { bb0 = __ldg(bias + col); bb1 = __ldg(bias + col + 1); }
            float2 lo = make_float2(acc[mt][nt][0] * scale + bb0,
                                    acc[mt][nt][1] * scale + bb1);
            float2 hi = make_float2(acc[mt][nt][2] * scale + bb0,
                                    acc[mt][nt][3] * scale + bb1);
            *(float2*)(C + (long)row * N + col) = lo;
            *(float2*)(C + (long)(row + 8) * N + col) = hi;
        }
    }
}

// ---------------------------------------------------------------- softmax over q (axis=1)
__global__ void k_softmax(float* __restrict__ P) {
    int tid = blockIdx.x * 256 + threadIdx.x;
    int b = tid >> 9, k = tid & 511;
    float* p = P + (long)b * (NS * NS) + k;
    float m = -1e30f;
    for (int q = 0; q < NS; q++) m = fmaxf(m, p[q * NS]);
    float s = 0.f;
    for (int q = 0; q < NS; q++) { float e = __expf(p[q * NS] - m); s += e; p[q * NS] = e; }
    float inv = 1.f / s;
    for (int q = 0; q < NS; q++) p[q * NS] *= inv;
}

// ---------------------------------------------------------------- z[b,s,:] -> Zt[(s,b),:]
__global__ void k_perm(const float4* __restrict__ in, float4* __restrict__ out) {
    long tid = (long)blockIdx.x * 256 + threadIdx.x;
    int row = (int)(tid >> 7), c = (int)(tid & 127);
    int s = row >> 6, b = row & 63;
    out[(long)row * 128 + c] = in[((long)b * NS + s) * 128 + c];
}

// ---------------------------------------------------------------- grid barrier
__device__ __forceinline__ void gbar() {
    __syncthreads();
    if (threadIdx.x == 0) {
        unsigned gen = g_phase;
        __threadfence();
        if (atomicAdd(&g_cnt, 1u) == gridDim.x - 1u) {
            g_cnt = 0;
            __threadfence();
            g_phase = gen + 1u;
        } else {
            while (g_phase == gen) { }
            __threadfence();
        }
    }
    __syncthreads();
}

// ---------------------------------------------------------------- tensor-core persistent GRU
// 64 CTAs x 256 threads. CTA owns 8 units x 3 gates = 24 W-rows (padded to M=32).
// Per step: P[32x64] = W[32x512] @ h^T via m16n8k8 tf32 mma.
// Wfrag: A-fragment-swizzled Wh in SMEM (built once): one LDS.128 per mma.
// hs: staged h_prev [64][516] — pad 516 makes B-frag LDS.32 conflict-free.
#define HPAD 516
#define WFRAG (64 * 2 * 32 * 4)                      // 16384 u32 = 64KB
#define GRU_SMEM ((WFRAG + NB * HPAD + 32 * 66) * 4) // 64KB + 132096B + 8448B = 206080B

__global__ __launch_bounds__(256) void k_gru(const float* __restrict__ GI,
                                             const float* __restrict__ Wh,
                                             const float* __restrict__ bh,
                                             float* __restrict__ Hout) {
    extern __shared__ float sm[];
    u32*   ws = (u32*)sm;                 // Wfrag [ks][mt][lane][4]
    float* hs = sm + WFRAG;               // staged h_prev [64][516]
    float* ps = sm + WFRAG + NB * HPAD;   // P [32][66]

    int t = threadIdx.x;
    int w = t >> 5, l = t & 31;
    int r = l >> 2, c = l & 3;
    int u0 = blockIdx.x * 8;

    // ---- build Wfrag once (rows j: gate=j>>3, unit=u0+(j&7); j>=24 -> 0)
    for (int idx = t; idx < 64 * 2 * 32; idx += 256) {
        int lane = idx & 31, mt = (idx >> 5) & 1, ks = idx >> 6;
        int rr = lane >> 2, cc = lane & 3;
        int j0 = mt * 16 + rr, j1 = j0 + 8;
        int k0 = ks * 8 + cc, k1 = k0 + 4;
        u32* dst = &ws[idx * 4];
        float v0 = (j0 < 24) ? Wh[((long)((j0 >> 3) * NA + u0 + (j0 & 7))) * NA + k0] : 0.f;
        float v1 = (j1 < 24) ? Wh[((long)((j1 >> 3) * NA + u0 + (j1 & 7))) * NA + k0] : 0.f;
        float v2 = (j0 < 24) ? Wh[((long)((j0 >> 3) * NA + u0 + (j0 & 7))) * NA + k1] : 0.f;
        float v3 = (j1 < 24) ? Wh[((long)((j1 >> 3) * NA + u0 + (j1 & 7))) * NA + k1] : 0.f;
        dst[0] = f2tf(v0); dst[1] = f2tf(v1); dst[2] = f2tf(v2); dst[3] = f2tf(v3);
    }

    // warp tiling: mt = w&1, ntiles 2*(w>>1), +1
    int mt = w & 1;
    int ntb = (w >> 1) * 2;

    // combine-phase assignment: item = b*8 + uu, two items per thread
    float bhv[2][3];
#pragma unroll
    for (int rep = 0; rep < 2; rep++) {
        int it = t + rep * 256;
        int uu = it & 7, u = u0 + uu;
        bhv[rep][0] = bh[u]; bhv[rep][1] = bh[NA + u]; bhv[rep][2] = bh[2 * NA + u];
    }
    __syncthreads();

    for (int s = 0; s < NS; s++) {
        // GI prefetch
        float gg[2][3];
#pragma unroll
        for (int rep = 0; rep < 2; rep++) {
            int it = t + rep * 256;
            int b = it >> 3, uu = it & 7, u = u0 + uu;
            const float* gi = GI + ((long)s * NB + b) * (3 * NA);
            gg[rep][0] = __ldg(gi + u);
            gg[rep][1] = __ldg(gi + NA + u);
            gg[rep][2] = __ldg(gi + 2 * NA + u);
        }

        // stage h_prev
        if (s == 0) {
            float4 zz = make_float4(0.f, 0.f, 0.f, 0.f);
#pragma unroll
            for (int i = 0; i < 32; i++) {
                int g = t + i * 256;
                *(float4*)&hs[(g >> 7) * HPAD + (g & 127) * 4] = zz;
            }
        } else {
            const float4* hg = (const float4*)g_h[s & 1];
#pragma unroll
            for (int i = 0; i < 32; i++) {
                int g = t + i * 256;
                float4 v = __ldcg(hg + g);
                *(float4*)&hs[(g >> 7) * HPAD + (g & 127) * 4] = v;
            }
        }
        __syncthreads();

        // ---- mma: P[32x64] = W @ h^T
        float acc[2][4];
#pragma unroll
        for (int nti = 0; nti < 2; nti++)
#pragma unroll
            for (int i = 0; i < 4; i++) acc[nti][i] = 0.f;

#pragma unroll 4
        for (int ks = 0; ks < 64; ks++) {
            uint4 af = *(const uint4*)&ws[((ks * 2 + mt) * 32 + l) * 4];
#pragma unroll
            for (int nti = 0; nti < 2; nti++) {
                int nt = ntb + nti;
                u32 b0 = ((const u32*)hs)[(nt * 8 + r) * HPAD + ks * 8 + c];
                u32 b1 = ((const u32*)hs)[(nt * 8 + r) * HPAD + ks * 8 + c + 4];
                asm volatile(
                    "mma.sync.aligned.m16n8k8.row.col.f32.tf32.tf32.f32 "
                    "{%0,%1,%2,%3},{%4,%5,%6,%7},{%8,%9},{%0,%1,%2,%3};"
                    : "+f"(acc[nti][0]), "+f"(acc[nti][1]),
                      "+f"(acc[nti][2]), "+f"(acc[nti][3])
                    : "r"(af.x), "r"(af.y), "r"(af.z), "r"(af.w),
                      "r"(b0), "r"(b1));
            }
        }
        // store P fragments
#pragma unroll
        for (int nti = 0; nti < 2; nti++) {
            int nt = ntb + nti;
            int row = mt * 16 + r, col = nt * 8 + c * 2;
            *(float2*)&ps[row * 66 + col] = make_float2(acc[nti][0], acc[nti][1]);
            *(float2*)&ps[(row + 8) * 66 + col] = make_float2(acc[nti][2], acc[nti][3]);
        }
        __syncthreads();

        // ---- gate combine (2 items per thread)
#pragma unroll
        for (int rep = 0; rep < 2; rep++) {
            int it = t + rep * 256;
            int b = it >> 3, uu = it & 7, u = u0 + uu;
            float ar = ps[uu * 66 + b];
            float az = ps[(8 + uu) * 66 + b];
            float an = ps[(16 + uu) * 66 + b];
            float rg = sigm(gg[rep][0] + ar + bhv[rep][0]);
            float zg = sigm(gg[rep][1] + az + bhv[rep][1]);
            float ng = tanhf(gg[rep][2] + rg * (an + bhv[rep][2]));
            float hp = hs[b * HPAD + u];
            float hval = (1.f - zg) * ng + zg * hp;
            g_h[(s & 1) ^ 1][b * NA + u] = hval;
            Hout[((long)s * NB + b) * NA + u] = hval;
        }
        gbar();
    }
}

// ---------------------------------------------------------------- head
__global__ void k_head(const float* __restrict__ Hs, const float* __restrict__ Wf,
                       const float* __restrict__ bf, float* __restrict__ out) {
    int warp = (blockIdx.x * 256 + threadIdx.x) >> 5;
    int lane = threadIdx.x & 31;
    const float* row = Hs + (long)warp * NA;
    float s = 0.f;
#pragma unroll
    for (int i = 0; i < 16; i++) s += row[lane + i * 32] * __ldg(&Wf[lane + i * 32]);
#pragma unroll
    for (int o = 16; o; o >>= 1) s += __shfl_xor_sync(0xffffffffu, s, o);
    if (lane == 0) {
        int ss = warp >> 6, b = warp & 63;
        out[b * NS + ss] = sigm(s + __ldg(bf));
    }
}

// ---------------------------------------------------------------- launch
extern "C" void kernel_launch(void* const* d_in, const int* in_sizes, int n_in,
                              void* d_out, int out_size) {
    const int*   cate  = (const int*)d_in[0];
    const float* cont  = (const float*)d_in[1];
    const float* emb   = (const float*)d_in[4];
    const float* Wcont = (const float*)d_in[5];
    const float* bcont = (const float*)d_in[6];
    const float* Wcomb = (const float*)d_in[7];
    const float* bcomb = (const float*)d_in[8];
    const float* Wq    = (const float*)d_in[9];
    const float* Wk    = (const float*)d_in[10];
    const float* Wv    = (const float*)d_in[11];
    const float* Wi    = (const float*)d_in[12];
    const float* Wh    = (const float*)d_in[13];
    const float* bi    = (const float*)d_in[14];
    const float* bh    = (const float*)d_in[15];
    const float* Wfin  = (const float*)d_in[16];
    const float* bfin  = (const float*)d_in[17];
    float* out = (float*)d_out;

    float *CE, *X, *Q, *K, *V, *GI;
    cudaGetSymbolAddress((void**)&CE, g_CE);
    cudaGetSymbolAddress((void**)&X,  g_X);
    cudaGetSymbolAddress((void**)&Q,  g_Q);
    cudaGetSymbolAddress((void**)&K,  g_K);
    cudaGetSymbolAddress((void**)&V,  g_V);
    cudaGetSymbolAddress((void**)&GI, g_GI);

    cudaFuncSetAttribute(k_gru, cudaFuncAttributeMaxDynamicSharedMemorySize, GRU_SMEM);

    const long SB2 = (long)NS * NS;
    const float iscl = 0.0441941738241592f; // 1/sqrt(512)

    k_prep<<<2, 256>>>(Wcont, bcont, Wcomb, bcomb);
    k_gather<<<BS * NH / 256, 256>>>(cate, emb);
    k_tgemm<0><<<dim3(8, 256, 1), 256>>>(CE, Wcomb, X, NH, NH, 0, 0, 0, nullptr, 1.f);
    k_extras<<<BS, 256>>>(cont);
    k_tgemm<0><<<dim3(8, 256, 1), 256>>>(X, Wq, Q, NA, NH, 0, 0, 0, nullptr, 1.f);
    k_tgemm<0><<<dim3(8, 256, 1), 256>>>(X, Wk, K, NA, NH, 0, 0, 0, nullptr, 1.f);
    k_tgemm<0><<<dim3(8, 256, 1), 256>>>(X, Wv, V, NA, NH, 0, 0, 0, nullptr, 1.f);
    k_tgemm<1><<<dim3(8, 4, 64), 256>>>(Q, K, CE, NS, NA, SB2, SB2, SB2, nullptr, iscl);
    k_softmax<<<128, 256>>>(CE);
    k_tgemm<0><<<dim3(8, 4, 64), 256>>>(CE, V, X, NA, NS, SB2, SB2, SB2, nullptr, 1.f);
    k_perm<<<BS * 128 / 256, 256>>>((const float4*)X, (float4*)Q);
    // layer 0
    k_tgemm<1><<<dim3(24, 256, 1), 256>>>(Q, Wi, GI, 3 * NA, NA, 0, 0, 0, bi, 1.f);
    k_gru<<<64, 256, GRU_SMEM>>>(GI, Wh, bh, K);
    // layer 1
    k_tgemm<1><<<dim3(24, 256, 1), 256>>>(K, Wi + 3 * NA * NA, GI, 3 * NA, NA, 0, 0, 0,
                                          bi + 3 * NA, 1.f);
    k_gru<<<64, 256, GRU_SMEM>>>(GI, Wh + 3 * NA * NA, bh + 3 * NA, V);
    // head
    k_head<<<BS / 8, 256>>>(V, Wfin, bfin, out);
}

// round 7
// speedup vs baseline: 3.7739x; 1.5798x over previous
#include <cuda_runtime.h>
#include <math.h>

typedef unsigned long long ull;
typedef unsigned int u32;

// ---------------------------------------------------------------- constants
#define NB   64
#define NS   512
#define NH   512
#define NA   512
#define NCC  4
#define NV   1000
#define NED  128
#define NFF  6
#define BS   32768          // NB*NS

// ---------------------------------------------------------------- scratch
__device__ float g_CE[BS * NH];       // gathered embeddings; reused as scores
__device__ float g_X [BS * NH];       // x; reused as z
__device__ float g_Q [BS * NA];       // Q; reused as Zt
__device__ float g_K [BS * NA];       // K; reused as GRU layer-0 output
__device__ float g_V [BS * NA];       // V; reused as GRU layer-1 output
__device__ float g_GI[BS * 3 * NA];   // GRU input gates (per layer)
__device__ float g_h [2][NB * NA];    // double-buffered hidden state
__device__ float g_Wcc[NFF * NH];
__device__ float g_bcc[NH];
__device__ u32   g_gc[256];           // per-group arrival counters (stride 32 = 128B)

// ---------------------------------------------------------------- helpers
__device__ __forceinline__ float sigm(float x) { return 1.f / (1.f + expf(-x)); }
__device__ __forceinline__ u32 f2tf(float x) {
    u32 r; asm("cvt.rna.tf32.f32 %0,%1;" : "=r"(r) : "f"(x)); return r;
}

// ---------------------------------------------------------------- prep
__global__ void k_prep(const float* __restrict__ Wcont, const float* __restrict__ bcont,
                       const float* __restrict__ Wcomb, const float* __restrict__ bcomb) {
    int j = blockIdx.x * 256 + threadIdx.x;
    if (j >= NH) return;
    float acc[NFF];
#pragma unroll
    for (int f = 0; f < NFF; f++) acc[f] = 0.f;
    float bacc = bcomb[j];
    for (int m = 0; m < NH; m++) {
        float w2 = Wcomb[(NH + m) * NH + j];
        bacc += bcont[m] * w2;
#pragma unroll
        for (int f = 0; f < NFF; f++) acc[f] += Wcont[f * NH + m] * w2;
    }
#pragma unroll
    for (int f = 0; f < NFF; f++) g_Wcc[f * NH + j] = acc[f];
    g_bcc[j] = bacc;
}

// ---------------------------------------------------------------- gather
__global__ void k_gather(const int* __restrict__ cate, const float* __restrict__ emb) {
    long i = (long)blockIdx.x * 256 + threadIdx.x;
    int n = (int)(i >> 9);
    int col = (int)(i & 511);
    int c = col >> 7, e = col & 127;
    int idx = cate[n * NCC + c];
    g_CE[i] = emb[((long)c * NV + idx) * NED + e];
}

// ---------------------------------------------------------------- extras
__global__ void k_extras(const float* __restrict__ cont) {
    int n = blockIdx.x;
    int j2 = threadIdx.x;
    __shared__ float c[NFF];
    if (threadIdx.x < NFF) c[threadIdx.x] = cont[n * NFF + threadIdx.x];
    __syncthreads();
    int s = n & (NS - 1);
    int j = j2 * 2;
    float v0 = g_bcc[j], v1 = g_bcc[j + 1];
#pragma unroll
    for (int f = 0; f < NFF; f++) {
        float cf = c[f];
        v0 += cf * g_Wcc[f * NH + j];
        v1 += cf * g_Wcc[f * NH + j + 1];
    }
    float ang = (float)s * expf(-(float)j * 0.0179889460f); // ln(10000)/512
    float sn, cs; sincosf(ang, &sn, &cs);
    v0 += sn; v1 += cs;
    float2* px = (float2*)(g_X + (long)n * NH);
    float2 o = px[j2];
    px[j2] = make_float2(o.x + v0, o.y + v1);
}

// ---------------------------------------------------------------- tf32 tensor-core GEMM
#define TBM 128
#define TBN 64
#define TBK 32

template <int TRB>
__global__ __launch_bounds__(256) void k_tgemm(
    const float* __restrict__ A, const float* __restrict__ Bm, float* __restrict__ C,
    int N, int K, long sA, long sB, long sC, const float* __restrict__ bias, float scale) {
    __shared__ u32 As[TBM][TBK + 4];
    __shared__ u32 Bs[2304];

    A  += (long)blockIdx.z * sA;
    Bm += (long)blockIdx.z * sB;
    C  += (long)blockIdx.z * sC;
    int m0 = blockIdx.y * TBM, n0 = blockIdx.x * TBN;
    int t = threadIdx.x;
    int warp = t >> 5, lane = t & 31;
    int wm = (warp >> 1) * 32;
    int wn = (warp & 1) * 32;
    int r = lane >> 2, c = lane & 3;

    float acc[2][4][4];
#pragma unroll
    for (int mt = 0; mt < 2; mt++)
#pragma unroll
        for (int nt = 0; nt < 4; nt++)
#pragma unroll
            for (int i = 0; i < 4; i++) acc[mt][nt][i] = 0.f;

    for (int k0 = 0; k0 < K; k0 += TBK) {
        __syncthreads();
#pragma unroll
        for (int rr = 0; rr < 4; rr++) {
            int q = t + rr * 256;
            int m = q >> 3, kc = q & 7;
            float4 v = *(const float4*)(A + (long)(m0 + m) * K + k0 + kc * 4);
            u32* dst = &As[m][kc * 4];
            dst[0] = f2tf(v.x); dst[1] = f2tf(v.y);
            dst[2] = f2tf(v.z); dst[3] = f2tf(v.w);
        }
        if (TRB == 0) {
#pragma unroll
            for (int rr = 0; rr < 2; rr++) {
                int q = t + rr * 256;
                int k = q >> 4, nc = q & 15;
                float4 v = *(const float4*)(Bm + (long)(k0 + k) * N + n0 + nc * 4);
                u32* dst = &Bs[k * 72 + nc * 4];
                dst[0] = f2tf(v.x); dst[1] = f2tf(v.y);
                dst[2] = f2tf(v.z); dst[3] = f2tf(v.w);
            }
        } else {
#pragma unroll
            for (int rr = 0; rr < 2; rr++) {
                int q = t + rr * 256;
                int n = q >> 3, kc = q & 7;
                float4 v = *(const float4*)(Bm + (long)(n0 + n) * K + k0 + kc * 4);
                u32* dst = &Bs[n * 36 + kc * 4];
                dst[0] = f2tf(v.x); dst[1] = f2tf(v.y);
                dst[2] = f2tf(v.z); dst[3] = f2tf(v.w);
            }
        }
        __syncthreads();
#pragma unroll
        for (int kb = 0; kb < TBK; kb += 8) {
            u32 a[2][4];
#pragma unroll
            for (int mt = 0; mt < 2; mt++) {
                int row = wm + mt * 16 + r;
                a[mt][0] = As[row][kb + c];
                a[mt][1] = As[row + 8][kb + c];
                a[mt][2] = As[row][kb + c + 4];
                a[mt][3] = As[row + 8][kb + c + 4];
            }
#pragma unroll
            for (int nt = 0; nt < 4; nt++) {
                int col = wn + nt * 8 + r;
                u32 b0, b1;
                if (TRB == 0) {
                    b0 = Bs[(kb + c) * 72 + col];
                    b1 = Bs[(kb + c + 4) * 72 + col];
                } else {
                    b0 = Bs[col * 36 + kb + c];
                    b1 = Bs[col * 36 + kb + c + 4];
                }
#pragma unroll
                for (int mt = 0; mt < 2; mt++) {
                    asm volatile(
                        "mma.sync.aligned.m16n8k8.row.col.f32.tf32.tf32.f32 "
                        "{%0,%1,%2,%3},{%4,%5,%6,%7},{%8,%9},{%0,%1,%2,%3};"
                        : "+f"(acc[mt][nt][0]), "+f"(acc[mt][nt][1]),
                          "+f"(acc[mt][nt][2]), "+f"(acc[mt][nt][3])
                        : "r"(a[mt][0]), "r"(a[mt][1]), "r"(a[mt][2]), "r"(a[mt][3]),
                          "r"(b0), "r"(b1));
                }
            }
        }
    }
#pragma unroll
    for (int mt = 0; mt < 2; mt++) {
#pragma unroll
        for (int nt = 0; nt < 4; nt++) {
            int row = m0 + wm + mt * 16 + r;
            int col = n0 + wn + nt * 8 + c * 2;
            float bb0 = 0.f, bb1 = 0.f;
            if (bias) { bb0 = __ldg(bias + col); bb1 = __ldg(bias + col + 1); }
            float2 lo = make_float2(acc[mt][nt][0] * scale + bb0,
                                    acc[mt][nt][1] * scale + bb1);
            float2 hi = make_float2(acc[mt][nt][2] * scale + bb0,
                                    acc[mt][nt][3] * scale + bb1);
            *(float2*)(C + (long)row * N + col) = lo;
            *(float2*)(C + (long)(row + 8) * N + col) = hi;
        }
    }
}

// ---------------------------------------------------------------- softmax over q (axis=1)
__global__ void k_softmax(float* __restrict__ P) {
    int tid = blockIdx.x * 256 + threadIdx.x;
    int b = tid >> 9, k = tid & 511;
    float* p = P + (long)b * (NS * NS) + k;
    float m = -1e30f;
    for (int q = 0; q < NS; q++) m = fmaxf(m, p[q * NS]);
    float s = 0.f;
    for (int q = 0; q < NS; q++) { float e = __expf(p[q * NS] - m); s += e; p[q * NS] = e; }
    float inv = 1.f / s;
    for (int q = 0; q < NS; q++) p[q * NS] *= inv;
}

// ---------------------------------------------------------------- z[b,s,:] -> Zt[(s,b),:]
__global__ void k_perm(const float4* __restrict__ in, float4* __restrict__ out) {
    long tid = (long)blockIdx.x * 256 + threadIdx.x;
    int row = (int)(tid >> 7), c = (int)(tid & 127);
    int s = row >> 6, b = row & 63;
    out[(long)row * 128 + c] = in[((long)b * NS + s) * 128 + c];
}

// ---------------------------------------------------------------- reset group counters
__global__ void k_rst() { g_gc[threadIdx.x] = 0; }

// ---------------------------------------------------------------- batch-grouped persistent GRU
// 128 CTAs = 8 groups x 16 CTAs. Group g owns batches 8g..8g+7 (independent recurrences!).
// CTA owns 32 units x 3 gates = 96 Wh rows, pre-swizzled tf32 A-fragments in SMEM.
// Per step: P[96x8] = W[96x512] @ h_g^T  (warps 0-5: one 16-row m-tile each, N=8).
// Group-local barrier: monotonic counter, one 128B line per group.
#define HSTR 516
#define WS_U32 (6 * 64 * 32 * 4)                 // 49152 u32 = 192KB
#define GRU_SMEM ((WS_U32 + 8 * HSTR + 96 * 11) * 4)   // 217,344 B

__global__ __launch_bounds__(256) void k_gru(const float* __restrict__ GI,
                                             const float* __restrict__ Wh,
                                             const float* __restrict__ bh,
                                             float* __restrict__ Hout) {
    extern __shared__ float sm[];
    u32*   ws = (u32*)sm;                  // Wfrag [ks][mt][lane][4]
    float* hs = sm + WS_U32;               // h_prev [8][516]
    float* ps = sm + WS_U32 + 8 * HSTR;    // P [96][11]
    const u32* hsu = (const u32*)hs;

    int t = threadIdx.x;
    int w = t >> 5, l = t & 31;
    int r = l >> 2, c = l & 3;
    int grp = blockIdx.x >> 4;             // 0..7
    int cig = blockIdx.x & 15;             // 0..15
    int u0  = cig * 32;
    int bg0 = grp * 8;
    volatile u32* bar = &g_gc[grp * 32];

    // ---- build Wfrag once: row j (0..95): gate=j>>5, unit=u0+(j&31)
    for (int idx = t; idx < 6 * 64 * 32; idx += 256) {
        int lane = idx & 31, mtks = idx >> 5;
        int mt = mtks % 6, ks = mtks / 6;
        int rr = lane >> 2, cc = lane & 3;
        int j0 = mt * 16 + rr, j1 = j0 + 8;
        int k0 = ks * 8 + cc, k1 = k0 + 4;
        long row0 = (long)((j0 >> 5) * NA + u0 + (j0 & 31)) * NA;
        long row1 = (long)((j1 >> 5) * NA + u0 + (j1 & 31)) * NA;
        uint4 v;
        v.x = f2tf(Wh[row0 + k0]);
        v.y = f2tf(Wh[row1 + k0]);
        v.z = f2tf(Wh[row0 + k1]);
        v.w = f2tf(Wh[row1 + k1]);
        *(uint4*)&ws[((ks * 6 + mt) * 32 + lane) * 4] = v;
    }

    // combine-phase constants: one item per thread: b = t>>5, uu = t&31
    int cb = t >> 5, cu = t & 31;
    int u = u0 + cu;
    float bhr = bh[u], bhz = bh[NA + u], bhn = bh[2 * NA + u];
    __syncthreads();

    for (int s = 0; s < NS; s++) {
        // GI prefetch (independent of h)
        const float* gi = GI + ((long)s * NB + bg0 + cb) * (3 * NA) + u;
        float gr = __ldg(gi), gz = __ldg(gi + NA), gn = __ldg(gi + 2 * NA);

        // group barrier: wait for all 16 CTAs to have finished step s-1
        if (s > 0) {
            if (t == 0) {
                u32 need = (u32)(16 * s);
                while (*bar < need) { }
                __threadfence();
            }
            __syncthreads();
        }

        // stage h_prev[8 batches][512] into SMEM (16KB, coalesced)
        if (s == 0) {
            float4 zz = make_float4(0.f, 0.f, 0.f, 0.f);
#pragma unroll
            for (int i = 0; i < 4; i++) {
                int g = t + i * 256;
                *(float4*)&hs[(g >> 7) * HSTR + (g & 127) * 4] = zz;
            }
        } else {
            const float4* hg = (const float4*)(g_h[s & 1] + bg0 * NA);
#pragma unroll
            for (int i = 0; i < 4; i++) {
                int g = t + i * 256;
                float4 v = __ldcg(hg + g);
                *(float4*)&hs[(g >> 7) * HSTR + (g & 127) * 4] = v;
            }
        }
        __syncthreads();

        // mma: warps 0-5, m-tile = warp, N=8, K=512
        if (w < 6) {
            float a0 = 0.f, a1 = 0.f, a2 = 0.f, a3 = 0.f;
#pragma unroll 8
            for (int ks = 0; ks < 64; ks++) {
                uint4 af = *(const uint4*)&ws[((ks * 6 + w) * 32 + l) * 4];
                u32 b0 = hsu[r * HSTR + ks * 8 + c];
                u32 b1 = hsu[r * HSTR + ks * 8 + c + 4];
                asm volatile(
                    "mma.sync.aligned.m16n8k8.row.col.f32.tf32.tf32.f32 "
                    "{%0,%1,%2,%3},{%4,%5,%6,%7},{%8,%9},{%0,%1,%2,%3};"
                    : "+f"(a0), "+f"(a1), "+f"(a2), "+f"(a3)
                    : "r"(af.x), "r"(af.y), "r"(af.z), "r"(af.w),
                      "r"(b0), "r"(b1));
            }
            int row = w * 16 + r;
            ps[row * 11 + c * 2]       = a0;
            ps[row * 11 + c * 2 + 1]   = a1;
            ps[(row + 8) * 11 + c * 2]     = a2;
            ps[(row + 8) * 11 + c * 2 + 1] = a3;
        }
        __syncthreads();

        // gate combine: 1 item/thread (batch cb, unit cu)
        float ar = ps[cu * 11 + cb];
        float az = ps[(32 + cu) * 11 + cb];
        float an = ps[(64 + cu) * 11 + cb];
        float rg = sigm(gr + ar + bhr);
        float zg = sigm(gz + az + bhz);
        float ng = tanhf(gn + rg * (an + bhn));
        float hp = hs[cb * HSTR + u];
        float hval = (1.f - zg) * ng + zg * hp;
        g_h[(s & 1) ^ 1][(bg0 + cb) * NA + u] = hval;
        Hout[((long)s * NB + bg0 + cb) * NA + u] = hval;
        __syncthreads();
        if (t == 0) { __threadfence(); atomicAdd((u32*)&g_gc[grp * 32], 1u); }
    }
}

// ---------------------------------------------------------------- head
__global__ void k_head(const float* __restrict__ Hs, const float* __restrict__ Wf,
                       const float* __restrict__ bf, float* __restrict__ out) {
    int warp = (blockIdx.x * 256 + threadIdx.x) >> 5;
    int lane = threadIdx.x & 31;
    const float* row = Hs + (long)warp * NA;
    float s = 0.f;
#pragma unroll
    for (int i = 0; i < 16; i++) s += row[lane + i * 32] * __ldg(&Wf[lane + i * 32]);
#pragma unroll
    for (int o = 16; o; o >>= 1) s += __shfl_xor_sync(0xffffffffu, s, o);
    if (lane == 0) {
        int ss = warp >> 6, b = warp & 63;
        out[b * NS + ss] = sigm(s + __ldg(bf));
    }
}

// ---------------------------------------------------------------- launch
extern "C" void kernel_launch(void* const* d_in, const int* in_sizes, int n_in,
                              void* d_out, int out_size) {
    const int*   cate  = (const int*)d_in[0];
    const float* cont  = (const float*)d_in[1];
    const float* emb   = (const float*)d_in[4];
    const float* Wcont = (const float*)d_in[5];
    const float* bcont = (const float*)d_in[6];
    const float* Wcomb = (const float*)d_in[7];
    const float* bcomb = (const float*)d_in[8];
    const float* Wq    = (const float*)d_in[9];
    const float* Wk    = (const float*)d_in[10];
    const float* Wv    = (const float*)d_in[11];
    const float* Wi    = (const float*)d_in[12];
    const float* Wh    = (const float*)d_in[13];
    const float* bi    = (const float*)d_in[14];
    const float* bh    = (const float*)d_in[15];
    const float* Wfin  = (const float*)d_in[16];
    const float* bfin  = (const float*)d_in[17];
    float* out = (float*)d_out;

    float *CE, *X, *Q, *K, *V, *GI;
    cudaGetSymbolAddress((void**)&CE, g_CE);
    cudaGetSymbolAddress((void**)&X,  g_X);
    cudaGetSymbolAddress((void**)&Q,  g_Q);
    cudaGetSymbolAddress((void**)&K,  g_K);
    cudaGetSymbolAddress((void**)&V,  g_V);
    cudaGetSymbolAddress((void**)&GI, g_GI);

    cudaFuncSetAttribute(k_gru, cudaFuncAttributeMaxDynamicSharedMemorySize, GRU_SMEM);

    const long SB2 = (long)NS * NS;
    const float iscl = 0.0441941738241592f; // 1/sqrt(512)

    k_prep<<<2, 256>>>(Wcont, bcont, Wcomb, bcomb);
    k_gather<<<BS * NH / 256, 256>>>(cate, emb);
    k_tgemm<0><<<dim3(8, 256, 1), 256>>>(CE, Wcomb, X, NH, NH, 0, 0, 0, nullptr, 1.f);
    k_extras<<<BS, 256>>>(cont);
    k_tgemm<0><<<dim3(8, 256, 1), 256>>>(X, Wq, Q, NA, NH, 0, 0, 0, nullptr, 1.f);
    k_tgemm<0><<<dim3(8, 256, 1), 256>>>(X, Wk, K, NA, NH, 0, 0, 0, nullptr, 1.f);
    k_tgemm<0><<<dim3(8, 256, 1), 256>>>(X, Wv, V, NA, NH, 0, 0, 0, nullptr, 1.f);
    k_tgemm<1><<<dim3(8, 4, 64), 256>>>(Q, K, CE, NS, NA, SB2, SB2, SB2, nullptr, iscl);
    k_softmax<<<128, 256>>>(CE);
    k_tgemm<0><<<dim3(8, 4, 64), 256>>>(CE, V, X, NA, NS, SB2, SB2, SB2, nullptr, 1.f);
    k_perm<<<BS * 128 / 256, 256>>>((const float4*)X, (float4*)Q);
    // layer 0
    k_tgemm<1><<<dim3(24, 256, 1), 256>>>(Q, Wi, GI, 3 * NA, NA, 0, 0, 0, bi, 1.f);
    k_rst<<<1, 256>>>();
    k_gru<<<128, 256, GRU_SMEM>>>(GI, Wh, bh, K);
    // layer 1
    k_tgemm<1><<<dim3(24, 256, 1), 256>>>(K, Wi + 3 * NA * NA, GI, 3 * NA, NA, 0, 0, 0,
                                          bi + 3 * NA, 1.f);
    k_rst<<<1, 256>>>();
    k_gru<<<128, 256, GRU_SMEM>>>(GI, Wh + 3 * NA * NA, bh + 3 * NA, V);
    // head
    k_head<<<BS / 8, 256>>>(V, Wfin, bfin, out);
}

// round 8
// speedup vs baseline: 3.9994x; 1.0598x over previous
#include <cuda_runtime.h>
#include <math.h>

typedef unsigned long long ull;
typedef unsigned int u32;

// ---------------------------------------------------------------- constants
#define NB   64
#define NS   512
#define NH   512
#define NA   512
#define NCC  4
#define NV   1000
#define NED  128
#define NFF  6
#define BS   32768          // NB*NS

// ---------------------------------------------------------------- scratch
__device__ float g_CE[BS * NH];       // scores
__device__ float g_X [BS * NH];       // x
__device__ float g_Q [BS * NA];       // Q; reused as Zt
__device__ float g_K [BS * NA];       // K; reused as GRU layer-0 output
__device__ float g_V [BS * NA];       // V; reused as GRU layer-1 output
__device__ float g_GI[BS * 3 * NA];   // GRU input gates (per layer)
__device__ float g_h [2][NB * NA];    // double-buffered hidden state
__device__ float g_Wcc[NFF * NH];
__device__ float g_bcc[NH];
__device__ u32   g_gc[256];           // per-group arrival counters

// ---------------------------------------------------------------- helpers
__device__ __forceinline__ float sigm(float x) { return 1.f / (1.f + expf(-x)); }
__device__ __forceinline__ u32 f2tf(float x) {
    u32 r; asm("cvt.rna.tf32.f32 %0,%1;" : "=r"(r) : "f"(x)); return r;
}
__device__ __forceinline__ void cpa16(u32 dst, const void* src) {
    asm volatile("cp.async.cg.shared.global [%0], [%1], 16;" :: "r"(dst), "l"(src));
}
__device__ __forceinline__ u32 cvsm(const void* p) {
    u32 r;
    asm("{ .reg .u64 t; cvta.to.shared.u64 t, %1; cvt.u32.u64 %0, t; }" : "=r"(r) : "l"(p));
    return r;
}

// ---------------------------------------------------------------- prep
__global__ void k_prep(const float* __restrict__ Wcont, const float* __restrict__ bcont,
                       const float* __restrict__ Wcomb, const float* __restrict__ bcomb) {
    int j = blockIdx.x * 256 + threadIdx.x;
    if (j >= NH) return;
    float acc[NFF];
#pragma unroll
    for (int f = 0; f < NFF; f++) acc[f] = 0.f;
    float bacc = bcomb[j];
    for (int m = 0; m < NH; m++) {
        float w2 = Wcomb[(NH + m) * NH + j];
        bacc += bcont[m] * w2;
#pragma unroll
        for (int f = 0; f < NFF; f++) acc[f] += Wcont[f * NH + m] * w2;
    }
#pragma unroll
    for (int f = 0; f < NFF; f++) g_Wcc[f * NH + j] = acc[f];
    g_bcc[j] = bacc;
}

// ---------------------------------------------------------------- extras
__global__ void k_extras(const float* __restrict__ cont) {
    int n = blockIdx.x;
    int j2 = threadIdx.x;
    __shared__ float c[NFF];
    if (threadIdx.x < NFF) c[threadIdx.x] = cont[n * NFF + threadIdx.x];
    __syncthreads();
    int s = n & (NS - 1);
    int j = j2 * 2;
    float v0 = g_bcc[j], v1 = g_bcc[j + 1];
#pragma unroll
    for (int f = 0; f < NFF; f++) {
        float cf = c[f];
        v0 += cf * g_Wcc[f * NH + j];
        v1 += cf * g_Wcc[f * NH + j + 1];
    }
    float ang = (float)s * expf(-(float)j * 0.0179889460f); // ln(10000)/512
    float sn, cs; sincosf(ang, &sn, &cs);
    v0 += sn; v1 += cs;
    float2* px = (float2*)(g_X + (long)n * NH);
    float2 o = px[j2];
    px[j2] = make_float2(o.x + v0, o.y + v1);
}

// ---------------------------------------------------------------- pipelined tf32 GEMM
// C[M,N] = scale*(A @ op(B)) + bias; tile 128x64, BK=32, 3-stage cp.async.
// A:[M,K] rm (or gathered embeddings when GATHER). TRB=0: B:[K,N]; TRB=1: B:[N,K].
// Output row stride = ldc (enables fused transpose).
#define ASZ 4608            // 128*36 u32
#define BSZ 2304
#define STGSZ (ASZ + BSZ)   // 6912 u32 = 27648 B
#define GEMM_SMEM (3 * STGSZ * 4)

template <int TRB, int GATHER>
__device__ __forceinline__ void g_load_stage(
    u32 smb, int st, const float* A, const float* Bm,
    const int* cate, const float* emb,
    int m0, int n0, int k0, int N, int K, int t) {
    u32 ab = smb + st * (STGSZ * 4);
#pragma unroll
    for (int rr = 0; rr < 4; rr++) {
        int q = t + rr * 256;
        int m = q >> 3, kc = q & 7;
        const float* src;
        if (GATHER) {
            int k = k0 + kc * 4;
            int cf = k >> 7, e = k & 127;
            int idx = __ldg(cate + (m0 + m) * NCC + cf);
            src = emb + ((long)cf * NV + idx) * NED + e;
        } else {
            src = A + (long)(m0 + m) * K + k0 + kc * 4;
        }
        cpa16(ab + (m * 36 + kc * 4) * 4, src);
    }
    u32 bb = ab + ASZ * 4;
#pragma unroll
    for (int rr = 0; rr < 2; rr++) {
        int q = t + rr * 256;
        if (TRB == 0) {
            int k = q >> 4, nc = q & 15;
            cpa16(bb + (k * 72 + nc * 4) * 4, Bm + (long)(k0 + k) * N + n0 + nc * 4);
        } else {
            int n = q >> 3, kc = q & 7;
            cpa16(bb + (n * 36 + kc * 4) * 4, Bm + (long)(n0 + n) * K + k0 + kc * 4);
        }
    }
}

template <int TRB, int GATHER>
__global__ __launch_bounds__(256) void k_tgemm(
    const float* __restrict__ A, const float* __restrict__ Bm, float* __restrict__ C,
    int N, int K, long sA, long sB, long sC, long ldc,
    const float* __restrict__ bias, float scale,
    const int* __restrict__ cate, const float* __restrict__ emb) {
    extern __shared__ u32 smp[];
    u32 smb = cvsm(smp);

    A  += (long)blockIdx.z * sA;
    Bm += (long)blockIdx.z * sB;
    C  += (long)blockIdx.z * sC;
    int m0 = blockIdx.y * 128, n0 = blockIdx.x * 64;
    int t = threadIdx.x;
    int warp = t >> 5, lane = t & 31;
    int wm = (warp >> 1) * 32;
    int wn = (warp & 1) * 32;
    int r = lane >> 2, c = lane & 3;
    int gm0 = GATHER ? (int)(blockIdx.y * 128) : m0;   // row base for gather index

    float acc[2][4][4];
#pragma unroll
    for (int mt = 0; mt < 2; mt++)
#pragma unroll
        for (int nt = 0; nt < 4; nt++)
#pragma unroll
            for (int i = 0; i < 4; i++) acc[mt][nt][i] = 0.f;

    int niter = K >> 5;
    g_load_stage<TRB, GATHER>(smb, 0, A, Bm, cate, emb, gm0, n0, 0, N, K, t);
    asm volatile("cp.async.commit_group;");
    g_load_stage<TRB, GATHER>(smb, 1, A, Bm, cate, emb, gm0, n0, 32, N, K, t);
    asm volatile("cp.async.commit_group;");

    for (int i = 0; i < niter; i++) {
        if (i == niter - 1) asm volatile("cp.async.wait_group 0;");
        else                asm volatile("cp.async.wait_group 1;");
        __syncthreads();
        if (i + 2 < niter) {
            g_load_stage<TRB, GATHER>(smb, (i + 2) % 3, A, Bm, cate, emb,
                                      gm0, n0, (i + 2) * 32, N, K, t);
            asm volatile("cp.async.commit_group;");
        }
        const u32* As_ = smp + (i % 3) * STGSZ;
        const u32* Bs_ = As_ + ASZ;
#pragma unroll
        for (int kb = 0; kb < 32; kb += 8) {
            u32 a[2][4];
#pragma unroll
            for (int mt = 0; mt < 2; mt++) {
                int row = wm + mt * 16 + r;
                a[mt][0] = As_[row * 36 + kb + c];
                a[mt][1] = As_[(row + 8) * 36 + kb + c];
                a[mt][2] = As_[row * 36 + kb + c + 4];
                a[mt][3] = As_[(row + 8) * 36 + kb + c + 4];
            }
#pragma unroll
            for (int nt = 0; nt < 4; nt++) {
                int col = wn + nt * 8 + r;
                u32 b0, b1;
                if (TRB == 0) {
                    b0 = Bs_[(kb + c) * 72 + col];
                    b1 = Bs_[(kb + c + 4) * 72 + col];
                } else {
                    b0 = Bs_[col * 36 + kb + c];
                    b1 = Bs_[col * 36 + kb + c + 4];
                }
#pragma unroll
                for (int mt = 0; mt < 2; mt++) {
                    asm volatile(
                        "mma.sync.aligned.m16n8k8.row.col.f32.tf32.tf32.f32 "
                        "{%0,%1,%2,%3},{%4,%5,%6,%7},{%8,%9},{%0,%1,%2,%3};"
                        : "+f"(acc[mt][nt][0]), "+f"(acc[mt][nt][1]),
                          "+f"(acc[mt][nt][2]), "+f"(acc[mt][nt][3])
                        : "r"(a[mt][0]), "r"(a[mt][1]), "r"(a[mt][2]), "r"(a[mt][3]),
                          "r"(b0), "r"(b1));
                }
            }
        }
    }
#pragma unroll
    for (int mt = 0; mt < 2; mt++) {
#pragma unroll
        for (int nt = 0; nt < 4; nt++) {
            int row = m0 + wm + mt * 16 + r;
            int col = n0 + wn + nt * 8 + c * 2;
            float bb0 = 0.f, bb1 = 0.f;
            if (bias) { bb0 = __ldg(bias + col); bb1 = __ldg(bias + col + 1); }
            float2 lo = make_float2(acc[mt][nt][0] * scale + bb0,
                                    acc[mt][nt][1] * scale + bb1);
            float2 hi = make_float2(acc[mt][nt][2] * scale + bb0,
                                    acc[mt][nt][3] * scale + bb1);
            *(float2*)(C + (long)row * ldc + col) = lo;
            *(float2*)(C + (long)(row + 8) * ldc + col) = hi;
        }
    }
}

// ---------------------------------------------------------------- softmax over q (axis=1)
__global__ void k_softmax(float* __restrict__ P) {
    int tid = blockIdx.x * 256 + threadIdx.x;
    int b = tid >> 9, k = tid & 511;
    float* p = P + (long)b * (NS * NS) + k;
    float m = -1e30f;
    for (int q = 0; q < NS; q++) m = fmaxf(m, p[q * NS]);
    float s = 0.f;
    for (int q = 0; q < NS; q++) { float e = __expf(p[q * NS] - m); s += e; p[q * NS] = e; }
    float inv = 1.f / s;
    for (int q = 0; q < NS; q++) p[q * NS] *= inv;
}

// ---------------------------------------------------------------- reset group counters
__global__ void k_rst() { g_gc[threadIdx.x] = 0; }

// ---------------------------------------------------------------- batch-grouped persistent GRU
#define HSTR 516
#define WS_U32 (6 * 64 * 32 * 4)
#define GRU_SMEM ((WS_U32 + 8 * HSTR + 96 * 11) * 4)

__global__ __launch_bounds__(256) void k_gru(const float* __restrict__ GI,
                                             const float* __restrict__ Wh,
                                             const float* __restrict__ bh,
                                             float* __restrict__ Hout) {
    extern __shared__ float sm[];
    u32*   ws = (u32*)sm;
    float* hs = sm + WS_U32;
    float* ps = sm + WS_U32 + 8 * HSTR;
    const u32* hsu = (const u32*)hs;

    int t = threadIdx.x;
    int w = t >> 5, l = t & 31;
    int r = l >> 2, c = l & 3;
    int grp = blockIdx.x >> 4;
    int cig = blockIdx.x & 15;
    int u0  = cig * 32;
    int bg0 = grp * 8;
    volatile u32* bar = &g_gc[grp * 32];

    for (int idx = t; idx < 6 * 64 * 32; idx += 256) {
        int lane = idx & 31, mtks = idx >> 5;
        int mt = mtks % 6, ks = mtks / 6;
        int rr = lane >> 2, cc = lane & 3;
        int j0 = mt * 16 + rr, j1 = j0 + 8;
        int k0 = ks * 8 + cc, k1 = k0 + 4;
        long row0 = (long)((j0 >> 5) * NA + u0 + (j0 & 31)) * NA;
        long row1 = (long)((j1 >> 5) * NA + u0 + (j1 & 31)) * NA;
        uint4 v;
        v.x = f2tf(Wh[row0 + k0]);
        v.y = f2tf(Wh[row1 + k0]);
        v.z = f2tf(Wh[row0 + k1]);
        v.w = f2tf(Wh[row1 + k1]);
        *(uint4*)&ws[((ks * 6 + mt) * 32 + lane) * 4] = v;
    }

    int cb = t >> 5, cu = t & 31;
    int u = u0 + cu;
    float bhr = bh[u], bhz = bh[NA + u], bhn = bh[2 * NA + u];
    __syncthreads();

    for (int s = 0; s < NS; s++) {
        const float* gi = GI + ((long)s * NB + bg0 + cb) * (3 * NA) + u;
        float gr = __ldg(gi), gz = __ldg(gi + NA), gn = __ldg(gi + 2 * NA);

        if (s > 0) {
            if (t == 0) {
                u32 need = (u32)(16 * s);
                while (*bar < need) { }
                __threadfence();
            }
            __syncthreads();
        }

        if (s == 0) {
            float4 zz = make_float4(0.f, 0.f, 0.f, 0.f);
#pragma unroll
            for (int i = 0; i < 4; i++) {
                int g = t + i * 256;
                *(float4*)&hs[(g >> 7) * HSTR + (g & 127) * 4] = zz;
            }
        } else {
            const float4* hg = (const float4*)(g_h[s & 1] + bg0 * NA);
#pragma unroll
            for (int i = 0; i < 4; i++) {
                int g = t + i * 256;
                float4 v = __ldcg(hg + g);
                *(float4*)&hs[(g >> 7) * HSTR + (g & 127) * 4] = v;
            }
        }
        __syncthreads();

        if (w < 6) {
            float a0 = 0.f, a1 = 0.f, a2 = 0.f, a3 = 0.f;
#pragma unroll 8
            for (int ks = 0; ks < 64; ks++) {
                uint4 af = *(const uint4*)&ws[((ks * 6 + w) * 32 + l) * 4];
                u32 b0 = hsu[r * HSTR + ks * 8 + c];
                u32 b1 = hsu[r * HSTR + ks * 8 + c + 4];
                asm volatile(
                    "mma.sync.aligned.m16n8k8.row.col.f32.tf32.tf32.f32 "
                    "{%0,%1,%2,%3},{%4,%5,%6,%7},{%8,%9},{%0,%1,%2,%3};"
                    : "+f"(a0), "+f"(a1), "+f"(a2), "+f"(a3)
                    : "r"(af.x), "r"(af.y), "r"(af.z), "r"(af.w),
                      "r"(b0), "r"(b1));
            }
            int row = w * 16 + r;
            ps[row * 11 + c * 2]           = a0;
            ps[row * 11 + c * 2 + 1]       = a1;
            ps[(row + 8) * 11 + c * 2]     = a2;
            ps[(row + 8) * 11 + c * 2 + 1] = a3;
        }
        __syncthreads();

        float ar = ps[cu * 11 + cb];
        float az = ps[(32 + cu) * 11 + cb];
        float an = ps[(64 + cu) * 11 + cb];
        float rg = sigm(gr + ar + bhr);
        float zg = sigm(gz + az + bhz);
        float ng = tanhf(gn + rg * (an + bhn));
        float hp = hs[cb * HSTR + u];
        float hval = (1.f - zg) * ng + zg * hp;
        g_h[(s & 1) ^ 1][(bg0 + cb) * NA + u] = hval;
        Hout[((long)s * NB + bg0 + cb) * NA + u] = hval;
        __syncthreads();
        if (t == 0) { __threadfence(); atomicAdd((u32*)&g_gc[grp * 32], 1u); }
    }
}

// ---------------------------------------------------------------- head
__global__ void k_head(const float* __restrict__ Hs, const float* __restrict__ Wf,
                       const float* __restrict__ bf, float* __restrict__ out) {
    int warp = (blockIdx.x * 256 + threadIdx.x) >> 5;
    int lane = threadIdx.x & 31;
    const float* row = Hs + (long)warp * NA;
    float s = 0.f;
#pragma unroll
    for (int i = 0; i < 16; i++) s += row[lane + i * 32] * __ldg(&Wf[lane + i * 32]);
#pragma unroll
    for (int o = 16; o; o >>= 1) s += __shfl_xor_sync(0xffffffffu, s, o);
    if (lane == 0) {
        int ss = warp >> 6, b = warp & 63;
        out[b * NS + ss] = sigm(s + __ldg(bf));
    }
}

// ---------------------------------------------------------------- launch
extern "C" void kernel_launch(void* const* d_in, const int* in_sizes, int n_in,
                              void* d_out, int out_size) {
    const int*   cate  = (const int*)d_in[0];
    const float* cont  = (const float*)d_in[1];
    const float* emb   = (const float*)d_in[4];
    const float* Wcont = (const float*)d_in[5];
    const float* bcont = (const float*)d_in[6];
    const float* Wcomb = (const float*)d_in[7];
    const float* bcomb = (const float*)d_in[8];
    const float* Wq    = (const float*)d_in[9];
    const float* Wk    = (const float*)d_in[10];
    const float* Wv    = (const float*)d_in[11];
    const float* Wi    = (const float*)d_in[12];
    const float* Wh    = (const float*)d_in[13];
    const float* bi    = (const float*)d_in[14];
    const float* bh    = (const float*)d_in[15];
    const float* Wfin  = (const float*)d_in[16];
    const float* bfin  = (const float*)d_in[17];
    float* out = (float*)d_out;

    float *CE, *X, *Q, *K, *V, *GI;
    cudaGetSymbolAddress((void**)&CE, g_CE);
    cudaGetSymbolAddress((void**)&X,  g_X);
    cudaGetSymbolAddress((void**)&Q,  g_Q);
    cudaGetSymbolAddress((void**)&K,  g_K);
    cudaGetSymbolAddress((void**)&V,  g_V);
    cudaGetSymbolAddress((void**)&GI, g_GI);

    cudaFuncSetAttribute(k_gru, cudaFuncAttributeMaxDynamicSharedMemorySize, GRU_SMEM);
    cudaFuncSetAttribute(k_tgemm<0, 0>, cudaFuncAttributeMaxDynamicSharedMemorySize, GEMM_SMEM);
    cudaFuncSetAttribute(k_tgemm<1, 0>, cudaFuncAttributeMaxDynamicSharedMemorySize, GEMM_SMEM);
    cudaFuncSetAttribute(k_tgemm<0, 1>, cudaFuncAttributeMaxDynamicSharedMemorySize, GEMM_SMEM);

    const long SB2 = (long)NS * NS;
    const float iscl = 0.0441941738241592f; // 1/sqrt(512)

    k_prep<<<2, 256>>>(Wcont, bcont, Wcomb, bcomb);
    // x = gather(emb, cate) @ Wcomb[0:512]   (gather fused into A-loads)
    k_tgemm<0, 1><<<dim3(8, 256, 1), 256, GEMM_SMEM>>>(
        nullptr, Wcomb, X, NH, NH, 0, 0, 0, NH, nullptr, 1.f, cate, emb);
    k_extras<<<BS, 256>>>(cont);
    // QKV
    k_tgemm<0, 0><<<dim3(8, 256, 1), 256, GEMM_SMEM>>>(
        X, Wq, Q, NA, NH, 0, 0, 0, NA, nullptr, 1.f, nullptr, nullptr);
    k_tgemm<0, 0><<<dim3(8, 256, 1), 256, GEMM_SMEM>>>(
        X, Wk, K, NA, NH, 0, 0, 0, NA, nullptr, 1.f, nullptr, nullptr);
    k_tgemm<0, 0><<<dim3(8, 256, 1), 256, GEMM_SMEM>>>(
        X, Wv, V, NA, NH, 0, 0, 0, NA, nullptr, 1.f, nullptr, nullptr);
    // scores = Q @ K^T / sqrt(A)
    k_tgemm<1, 0><<<dim3(8, 4, 64), 256, GEMM_SMEM>>>(
        Q, K, CE, NS, NA, SB2, SB2, SB2, NS, nullptr, iscl, nullptr, nullptr);
    k_softmax<<<128, 256>>>(CE);
    // Zt[(s,b),:] = (P @ V)[b,s,:]  — transpose fused via ldc/sC
    k_tgemm<0, 0><<<dim3(8, 4, 64), 256, GEMM_SMEM>>>(
        CE, V, Q, NA, NS, SB2, SB2, (long)NA, (long)NB * NA, nullptr, 1.f, nullptr, nullptr);
    // layer 0
    k_tgemm<1, 0><<<dim3(24, 256, 1), 256, GEMM_SMEM>>>(
        Q, Wi, GI, 3 * NA, NA, 0, 0, 0, 3 * NA, bi, 1.f, nullptr, nullptr);
    k_rst<<<1, 256>>>();
    k_gru<<<128, 256, GRU_SMEM>>>(GI, Wh, bh, K);
    // layer 1
    k_tgemm<1, 0><<<dim3(24, 256, 1), 256, GEMM_SMEM>>>(
        K, Wi + 3 * NA * NA, GI, 3 * NA, NA, 0, 0, 0, 3 * NA, bi + 3 * NA, 1.f,
        nullptr, nullptr);
    k_rst<<<1, 256>>>();
    k_gru<<<128, 256, GRU_SMEM>>>(GI, Wh + 3 * NA * NA, bh + 3 * NA, V);
    // head
    k_head<<<BS / 8, 256>>>(V, Wfin, bfin, out);
}

// round 9
// speedup vs baseline: 4.2572x; 1.0645x over previous
#include <cuda_runtime.h>
#include <math.h>

typedef unsigned long long ull;
typedef unsigned int u32;

// ---------------------------------------------------------------- constants
#define NB   64
#define NS   512
#define NH   512
#define NA   512
#define NCC  4
#define NV   1000
#define NED  128
#define NFF  6
#define BS   32768          // NB*NS

// ---------------------------------------------------------------- scratch
__device__ float g_CE[BS * NH];       // scores
__device__ float g_X [BS * NH];       // x
__device__ float g_Q [BS * NA];       // Q; reused as Zt
__device__ float g_K [BS * NA];       // K; reused as GRU layer-0 output
__device__ float g_V [BS * NA];       // V; reused as GRU layer-1 output
__device__ float g_GI[BS * 3 * NA];   // GRU input gates (per layer)
__device__ float g_h [2][NB * NA];    // double-buffered hidden state
__device__ float g_Wcc[NFF * NH];
__device__ float g_bcc[NH];
__device__ u32   g_gc[256];           // per-group arrival counters

// ---------------------------------------------------------------- helpers
__device__ __forceinline__ float sigm(float x) { return 1.f / (1.f + expf(-x)); }
__device__ __forceinline__ u32 f2tf(float x) {
    u32 r; asm("cvt.rna.tf32.f32 %0,%1;" : "=r"(r) : "f"(x)); return r;
}
__device__ __forceinline__ void cpa16(u32 dst, const void* src) {
    asm volatile("cp.async.cg.shared.global [%0], [%1], 16;" :: "r"(dst), "l"(src));
}
__device__ __forceinline__ u32 cvsm(const void* p) {
    u32 r;
    asm("{ .reg .u64 t; cvta.to.shared.u64 t, %1; cvt.u32.u64 %0, t; }" : "=r"(r) : "l"(p));
    return r;
}

// ---------------------------------------------------------------- prep
__global__ void k_prep(const float* __restrict__ Wcont, const float* __restrict__ bcont,
                       const float* __restrict__ Wcomb, const float* __restrict__ bcomb) {
    int j = blockIdx.x * 256 + threadIdx.x;
    if (j >= NH) return;
    float acc[NFF];
#pragma unroll
    for (int f = 0; f < NFF; f++) acc[f] = 0.f;
    float bacc = bcomb[j];
    for (int m = 0; m < NH; m++) {
        float w2 = Wcomb[(NH + m) * NH + j];
        bacc += bcont[m] * w2;
#pragma unroll
        for (int f = 0; f < NFF; f++) acc[f] += Wcont[f * NH + m] * w2;
    }
#pragma unroll
    for (int f = 0; f < NFF; f++) g_Wcc[f * NH + j] = acc[f];
    g_bcc[j] = bacc;
}

// ---------------------------------------------------------------- extras
__global__ void k_extras(const float* __restrict__ cont) {
    int n = blockIdx.x;
    int j2 = threadIdx.x;
    __shared__ float c[NFF];
    if (threadIdx.x < NFF) c[threadIdx.x] = cont[n * NFF + threadIdx.x];
    __syncthreads();
    int s = n & (NS - 1);
    int j = j2 * 2;
    float v0 = g_bcc[j], v1 = g_bcc[j + 1];
#pragma unroll
    for (int f = 0; f < NFF; f++) {
        float cf = c[f];
        v0 += cf * g_Wcc[f * NH + j];
        v1 += cf * g_Wcc[f * NH + j + 1];
    }
    float ang = (float)s * expf(-(float)j * 0.0179889460f); // ln(10000)/512
    float sn, cs; sincosf(ang, &sn, &cs);
    v0 += sn; v1 += cs;
    float2* px = (float2*)(g_X + (long)n * NH);
    float2 o = px[j2];
    px[j2] = make_float2(o.x + v0, o.y + v1);
}

// ---------------------------------------------------------------- pipelined tf32 GEMM, 128x128 tile
// C[M,N] = scale*(A @ op(B)) + bias; BK=32, 3-stage cp.async, raw fp32 bits as tf32.
// 8 warps (2x4), warp tile 64x32 (4 m-tiles x 4 n-tiles of m16n8k8). ldc = output row stride.
#define ASZ 4608                 // 128*36 u32
#define BSZ 4608                 // max(32*136, 128*36)
#define STGSZ (ASZ + BSZ)        // 9216 u32 = 36864 B
#define GEMM_SMEM (3 * STGSZ * 4)   // 110,592 B

template <int TRB, int GATHER>
__device__ __forceinline__ void g_load_stage(
    u32 smb, int st, const float* A, const float* Bm,
    const int* cate, const float* emb,
    int m0, int n0, int k0, int N, int K, int t) {
    u32 ab = smb + st * (STGSZ * 4);
#pragma unroll
    for (int rr = 0; rr < 4; rr++) {
        int q = t + rr * 256;
        int m = q >> 3, kc = q & 7;
        const float* src;
        if (GATHER) {
            int k = k0 + kc * 4;
            int cf = k >> 7, e = k & 127;
            int idx = __ldg(cate + (m0 + m) * NCC + cf);
            src = emb + ((long)cf * NV + idx) * NED + e;
        } else {
            src = A + (long)(m0 + m) * K + k0 + kc * 4;
        }
        cpa16(ab + (m * 36 + kc * 4) * 4, src);
    }
    u32 bb = ab + ASZ * 4;
#pragma unroll
    for (int rr = 0; rr < 4; rr++) {
        int q = t + rr * 256;
        if (TRB == 0) {
            int k = q >> 5, nc = q & 31;
            cpa16(bb + (k * 136 + nc * 4) * 4, Bm + (long)(k0 + k) * N + n0 + nc * 4);
        } else {
            int n = q >> 3, kc = q & 7;
            cpa16(bb + (n * 36 + kc * 4) * 4, Bm + (long)(n0 + n) * K + k0 + kc * 4);
        }
    }
}

template <int TRB, int GATHER>
__global__ __launch_bounds__(256, 2) void k_tgemm(
    const float* __restrict__ A, const float* __restrict__ Bm, float* __restrict__ C,
    int N, int K, long sA, long sB, long sC, long ldc,
    const float* __restrict__ bias, float scale,
    const int* __restrict__ cate, const float* __restrict__ emb) {
    extern __shared__ u32 smp[];
    u32 smb = cvsm(smp);

    A  += (long)blockIdx.z * sA;
    Bm += (long)blockIdx.z * sB;
    C  += (long)blockIdx.z * sC;
    int m0 = blockIdx.y * 128, n0 = blockIdx.x * 128;
    int t = threadIdx.x;
    int warp = t >> 5, lane = t & 31;
    int wm = (warp >> 2) * 64;          // 2 warp-rows
    int wn = (warp & 3) * 32;           // 4 warp-cols
    int r = lane >> 2, c = lane & 3;

    float acc[4][4][4];
#pragma unroll
    for (int mt = 0; mt < 4; mt++)
#pragma unroll
        for (int nt = 0; nt < 4; nt++)
#pragma unroll
            for (int i = 0; i < 4; i++) acc[mt][nt][i] = 0.f;

    int niter = K >> 5;
    g_load_stage<TRB, GATHER>(smb, 0, A, Bm, cate, emb, m0, n0, 0, N, K, t);
    asm volatile("cp.async.commit_group;");
    g_load_stage<TRB, GATHER>(smb, 1, A, Bm, cate, emb, m0, n0, 32, N, K, t);
    asm volatile("cp.async.commit_group;");

    for (int i = 0; i < niter; i++) {
        if (i == niter - 1) asm volatile("cp.async.wait_group 0;");
        else                asm volatile("cp.async.wait_group 1;");
        __syncthreads();
        if (i + 2 < niter) {
            g_load_stage<TRB, GATHER>(smb, (i + 2) % 3, A, Bm, cate, emb,
                                      m0, n0, (i + 2) * 32, N, K, t);
            asm volatile("cp.async.commit_group;");
        }
        const u32* As_ = smp + (i % 3) * STGSZ;
        const u32* Bs_ = As_ + ASZ;
#pragma unroll
        for (int kb = 0; kb < 32; kb += 8) {
            u32 a[4][4];
#pragma unroll
            for (int mt = 0; mt < 4; mt++) {
                int row = wm + mt * 16 + r;
                a[mt][0] = As_[row * 36 + kb + c];
                a[mt][1] = As_[(row + 8) * 36 + kb + c];
                a[mt][2] = As_[row * 36 + kb + c + 4];
                a[mt][3] = As_[(row + 8) * 36 + kb + c + 4];
            }
#pragma unroll
            for (int nt = 0; nt < 4; nt++) {
                int col = wn + nt * 8 + r;
                u32 b0, b1;
                if (TRB == 0) {
                    b0 = Bs_[(kb + c) * 136 + col];
                    b1 = Bs_[(kb + c + 4) * 136 + col];
                } else {
                    b0 = Bs_[col * 36 + kb + c];
                    b1 = Bs_[col * 36 + kb + c + 4];
                }
#pragma unroll
                for (int mt = 0; mt < 4; mt++) {
                    asm volatile(
                        "mma.sync.aligned.m16n8k8.row.col.f32.tf32.tf32.f32 "
                        "{%0,%1,%2,%3},{%4,%5,%6,%7},{%8,%9},{%0,%1,%2,%3};"
                        : "+f"(acc[mt][nt][0]), "+f"(acc[mt][nt][1]),
                          "+f"(acc[mt][nt][2]), "+f"(acc[mt][nt][3])
                        : "r"(a[mt][0]), "r"(a[mt][1]), "r"(a[mt][2]), "r"(a[mt][3]),
                          "r"(b0), "r"(b1));
                }
            }
        }
    }
#pragma unroll
    for (int mt = 0; mt < 4; mt++) {
#pragma unroll
        for (int nt = 0; nt < 4; nt++) {
            int row = m0 + wm + mt * 16 + r;
            int col = n0 + wn + nt * 8 + c * 2;
            float bb0 = 0.f, bb1 = 0.f;
            if (bias) { bb0 = __ldg(bias + col); bb1 = __ldg(bias + col + 1); }
            float2 lo = make_float2(acc[mt][nt][0] * scale + bb0,
                                    acc[mt][nt][1] * scale + bb1);
            float2 hi = make_float2(acc[mt][nt][2] * scale + bb0,
                                    acc[mt][nt][3] * scale + bb1);
            *(float2*)(C + (long)row * ldc + col) = lo;
            *(float2*)(C + (long)(row + 8) * ldc + col) = hi;
        }
    }
}

// ---------------------------------------------------------------- softmax over q (axis=1), smem-staged
// CTA = (batch b, 64-column k-block). Slab [512 q][64 k] staged in smem (stride 72).
#define SMX_STR 72
#define SMX_SMEM ((512 * SMX_STR + 256) * 4)

__global__ __launch_bounds__(256) void k_softmax(float* __restrict__ P) {
    extern __shared__ float sx[];
    float* red = sx + 512 * SMX_STR;
    int b = blockIdx.y, k0 = blockIdx.x * 64;
    int t = threadIdx.x;
    float* base = P + (long)b * (NS * NS) + k0;

    // stage: 16 rows per iteration (float4)
#pragma unroll
    for (int i = 0; i < 32; i++) {
        int q = i * 16 + (t >> 4), c4 = (t & 15) * 4;
        float4 v = *(const float4*)(base + (long)q * NS + c4);
        *(float4*)&sx[q * SMX_STR + c4] = v;
    }
    __syncthreads();

    int tc = t & 63, tq = t >> 6;           // column, q-quarter
    // pass 1: max
    float m = -1e30f;
#pragma unroll 8
    for (int q = tq * 128; q < tq * 128 + 128; q++) m = fmaxf(m, sx[q * SMX_STR + tc]);
    red[t] = m;
    __syncthreads();
    if (t < 64) red[t] = fmaxf(fmaxf(red[t], red[64 + t]), fmaxf(red[128 + t], red[192 + t]));
    __syncthreads();
    m = red[tc];
    __syncthreads();
    // pass 2: exp + sum
    float s = 0.f;
#pragma unroll 8
    for (int q = tq * 128; q < tq * 128 + 128; q++) {
        float e = __expf(sx[q * SMX_STR + tc] - m);
        sx[q * SMX_STR + tc] = e;
        s += e;
    }
    red[t] = s;
    __syncthreads();
    if (t < 64) red[t] = (red[t] + red[64 + t]) + (red[128 + t] + red[192 + t]);
    __syncthreads();
    float inv = 1.f / red[tc];
    // pass 3: normalize + write back (coalesced)
#pragma unroll 8
    for (int q = tq * 128; q < tq * 128 + 128; q++)
        base[(long)q * NS + tc] = sx[q * SMX_STR + tc] * inv;
}

// ---------------------------------------------------------------- reset group counters
__global__ void k_rst() { g_gc[threadIdx.x] = 0; }

// ---------------------------------------------------------------- batch-grouped persistent GRU
#define HSTR 516
#define WS_U32 (6 * 64 * 32 * 4)
#define GRU_SMEM ((WS_U32 + 8 * HSTR + 96 * 11) * 4)

__global__ __launch_bounds__(256) void k_gru(const float* __restrict__ GI,
                                             const float* __restrict__ Wh,
                                             const float* __restrict__ bh,
                                             float* __restrict__ Hout) {
    extern __shared__ float sm[];
    u32*   ws = (u32*)sm;
    float* hs = sm + WS_U32;
    float* ps = sm + WS_U32 + 8 * HSTR;
    const u32* hsu = (const u32*)hs;

    int t = threadIdx.x;
    int w = t >> 5, l = t & 31;
    int r = l >> 2, c = l & 3;
    int grp = blockIdx.x >> 4;
    int cig = blockIdx.x & 15;
    int u0  = cig * 32;
    int bg0 = grp * 8;
    volatile u32* bar = &g_gc[grp * 32];

    for (int idx = t; idx < 6 * 64 * 32; idx += 256) {
        int lane = idx & 31, mtks = idx >> 5;
        int mt = mtks % 6, ks = mtks / 6;
        int rr = lane >> 2, cc = lane & 3;
        int j0 = mt * 16 + rr, j1 = j0 + 8;
        int k0 = ks * 8 + cc, k1 = k0 + 4;
        long row0 = (long)((j0 >> 5) * NA + u0 + (j0 & 31)) * NA;
        long row1 = (long)((j1 >> 5) * NA + u0 + (j1 & 31)) * NA;
        uint4 v;
        v.x = f2tf(Wh[row0 + k0]);
        v.y = f2tf(Wh[row1 + k0]);
        v.z = f2tf(Wh[row0 + k1]);
        v.w = f2tf(Wh[row1 + k1]);
        *(uint4*)&ws[((ks * 6 + mt) * 32 + lane) * 4] = v;
    }

    int cb = t >> 5, cu = t & 31;
    int u = u0 + cu;
    float bhr = bh[u], bhz = bh[NA + u], bhn = bh[2 * NA + u];
    __syncthreads();

    for (int s = 0; s < NS; s++) {
        const float* gi = GI + ((long)s * NB + bg0 + cb) * (3 * NA) + u;
        float gr = __ldg(gi), gz = __ldg(gi + NA), gn = __ldg(gi + 2 * NA);

        if (s > 0) {
            if (t == 0) {
                u32 need = (u32)(16 * s);
                while (*bar < need) { }
                __threadfence();
            }
            __syncthreads();
        }

        if (s == 0) {
            float4 zz = make_float4(0.f, 0.f, 0.f, 0.f);
#pragma unroll
            for (int i = 0; i < 4; i++) {
                int g = t + i * 256;
                *(float4*)&hs[(g >> 7) * HSTR + (g & 127) * 4] = zz;
            }
        } else {
            const float4* hg = (const float4*)(g_h[s & 1] + bg0 * NA);
#pragma unroll
            for (int i = 0; i < 4; i++) {
                int g = t + i * 256;
                float4 v = __ldcg(hg + g);
                *(float4*)&hs[(g >> 7) * HSTR + (g & 127) * 4] = v;
            }
        }
        __syncthreads();

        if (w < 6) {
            float a0 = 0.f, a1 = 0.f, a2 = 0.f, a3 = 0.f;
#pragma unroll 8
            for (int ks = 0; ks < 64; ks++) {
                uint4 af = *(const uint4*)&ws[((ks * 6 + w) * 32 + l) * 4];
                u32 b0 = hsu[r * HSTR + ks * 8 + c];
                u32 b1 = hsu[r * HSTR + ks * 8 + c + 4];
                asm volatile(
                    "mma.sync.aligned.m16n8k8.row.col.f32.tf32.tf32.f32 "
                    "{%0,%1,%2,%3},{%4,%5,%6,%7},{%8,%9},{%0,%1,%2,%3};"
                    : "+f"(a0), "+f"(a1), "+f"(a2), "+f"(a3)
                    : "r"(af.x), "r"(af.y), "r"(af.z), "r"(af.w),
                      "r"(b0), "r"(b1));
            }
            int row = w * 16 + r;
            ps[row * 11 + c * 2]           = a0;
            ps[row * 11 + c * 2 + 1]       = a1;
            ps[(row + 8) * 11 + c * 2]     = a2;
            ps[(row + 8) * 11 + c * 2 + 1] = a3;
        }
        __syncthreads();

        float ar = ps[cu * 11 + cb];
        float az = ps[(32 + cu) * 11 + cb];
        float an = ps[(64 + cu) * 11 + cb];
        float rg = sigm(gr + ar + bhr);
        float zg = sigm(gz + az + bhz);
        float ng = tanhf(gn + rg * (an + bhn));
        float hp = hs[cb * HSTR + u];
        float hval = (1.f - zg) * ng + zg * hp;
        g_h[(s & 1) ^ 1][(bg0 + cb) * NA + u] = hval;
        Hout[((long)s * NB + bg0 + cb) * NA + u] = hval;
        __syncthreads();
        if (t == 0) { __threadfence(); atomicAdd((u32*)&g_gc[grp * 32], 1u); }
    }
}

// ---------------------------------------------------------------- head
__global__ void k_head(const float* __restrict__ Hs, const float* __restrict__ Wf,
                       const float* __restrict__ bf, float* __restrict__ out) {
    int warp = (blockIdx.x * 256 + threadIdx.x) >> 5;
    int lane = threadIdx.x & 31;
    const float* row = Hs + (long)warp * NA;
    float s = 0.f;
#pragma unroll
    for (int i = 0; i < 16; i++) s += row[lane + i * 32] * __ldg(&Wf[lane + i * 32]);
#pragma unroll
    for (int o = 16; o; o >>= 1) s += __shfl_xor_sync(0xffffffffu, s, o);
    if (lane == 0) {
        int ss = warp >> 6, b = warp & 63;
        out[b * NS + ss] = sigm(s + __ldg(bf));
    }
}

// ---------------------------------------------------------------- launch
extern "C" void kernel_launch(void* const* d_in, const int* in_sizes, int n_in,
                              void* d_out, int out_size) {
    const int*   cate  = (const int*)d_in[0];
    const float* cont  = (const float*)d_in[1];
    const float* emb   = (const float*)d_in[4];
    const float* Wcont = (const float*)d_in[5];
    const float* bcont = (const float*)d_in[6];
    const float* Wcomb = (const float*)d_in[7];
    const float* bcomb = (const float*)d_in[8];
    const float* Wq    = (const float*)d_in[9];
    const float* Wk    = (const float*)d_in[10];
    const float* Wv    = (const float*)d_in[11];
    const float* Wi    = (const float*)d_in[12];
    const float* Wh    = (const float*)d_in[13];
    const float* bi    = (const float*)d_in[14];
    const float* bh    = (const float*)d_in[15];
    const float* Wfin  = (const float*)d_in[16];
    const float* bfin  = (const float*)d_in[17];
    float* out = (float*)d_out;

    float *CE, *X, *Q, *K, *V, *GI;
    cudaGetSymbolAddress((void**)&CE, g_CE);
    cudaGetSymbolAddress((void**)&X,  g_X);
    cudaGetSymbolAddress((void**)&Q,  g_Q);
    cudaGetSymbolAddress((void**)&K,  g_K);
    cudaGetSymbolAddress((void**)&V,  g_V);
    cudaGetSymbolAddress((void**)&GI, g_GI);

    cudaFuncSetAttribute(k_gru, cudaFuncAttributeMaxDynamicSharedMemorySize, GRU_SMEM);
    cudaFuncSetAttribute(k_tgemm<0, 0>, cudaFuncAttributeMaxDynamicSharedMemorySize, GEMM_SMEM);
    cudaFuncSetAttribute(k_tgemm<1, 0>, cudaFuncAttributeMaxDynamicSharedMemorySize, GEMM_SMEM);
    cudaFuncSetAttribute(k_tgemm<0, 1>, cudaFuncAttributeMaxDynamicSharedMemorySize, GEMM_SMEM);
    cudaFuncSetAttribute(k_softmax, cudaFuncAttributeMaxDynamicSharedMemorySize, SMX_SMEM);

    const long SB2 = (long)NS * NS;
    const float iscl = 0.0441941738241592f; // 1/sqrt(512)

    k_prep<<<2, 256>>>(Wcont, bcont, Wcomb, bcomb);
    // x = gather(emb, cate) @ Wcomb[0:512]
    k_tgemm<0, 1><<<dim3(4, 256, 1), 256, GEMM_SMEM>>>(
        nullptr, Wcomb, X, NH, NH, 0, 0, 0, NH, nullptr, 1.f, cate, emb);
    k_extras<<<BS, 256>>>(cont);
    // QKV
    k_tgemm<0, 0><<<dim3(4, 256, 1), 256, GEMM_SMEM>>>(
        X, Wq, Q, NA, NH, 0, 0, 0, NA, nullptr, 1.f, nullptr, nullptr);
    k_tgemm<0, 0><<<dim3(4, 256, 1), 256, GEMM_SMEM>>>(
        X, Wk, K, NA, NH, 0, 0, 0, NA, nullptr, 1.f, nullptr, nullptr);
    k_tgemm<0, 0><<<dim3(4, 256, 1), 256, GEMM_SMEM>>>(
        X, Wv, V, NA, NH, 0, 0, 0, NA, nullptr, 1.f, nullptr, nullptr);
    // scores = Q @ K^T / sqrt(A)
    k_tgemm<1, 0><<<dim3(4, 4, 64), 256, GEMM_SMEM>>>(
        Q, K, CE, NS, NA, SB2, SB2, SB2, NS, nullptr, iscl, nullptr, nullptr);
    k_softmax<<<dim3(8, 64), 256, SMX_SMEM>>>(CE);
    // Zt[(s,b),:] = (P @ V)[b,s,:]  — transpose fused via ldc/sC
    k_tgemm<0, 0><<<dim3(4, 4, 64), 256, GEMM_SMEM>>>(
        CE, V, Q, NA, NS, SB2, SB2, (long)NA, (long)NB * NA, nullptr, 1.f, nullptr, nullptr);
    // layer 0
    k_tgemm<1, 0><<<dim3(12, 256, 1), 256, GEMM_SMEM>>>(
        Q, Wi, GI, 3 * NA, NA, 0, 0, 0, 3 * NA, bi, 1.f, nullptr, nullptr);
    k_rst<<<1, 256>>>();
    k_gru<<<128, 256, GRU_SMEM>>>(GI, Wh, bh, K);
    // layer 1
    k_tgemm<1, 0><<<dim3(12, 256, 1), 256, GEMM_SMEM>>>(
        K, Wi + 3 * NA * NA, GI, 3 * NA, NA, 0, 0, 0, 3 * NA, bi + 3 * NA, 1.f,
        nullptr, nullptr);
    k_rst<<<1, 256>>>();
    k_gru<<<128, 256, GRU_SMEM>>>(GI, Wh + 3 * NA * NA, bh + 3 * NA, V);
    // head
    k_head<<<BS / 8, 256>>>(V, Wfin, bfin, out);
}